// round 2
// baseline (speedup 1.0000x reference)
#include <cuda_runtime.h>
#include <math.h>

#define Bv 8
#define Sv 1024
#define Dv 512
#define Hv 256
#define Nv 64
#define SDv 128
#define NHv 4
#define DHv 64

// Scratch (static device globals: no allocations allowed)
__device__ float g_qwx[(size_t)Bv * Sv * 512];   // per token: [q(128) | wr(128) | xh0(256)]
__device__ float g_ypre[(size_t)Bv * Sv * Dv];   // pre-LN outputs

// ---------------------------------------------------------------------------
// Kernel 1: precompute q/wr/xh0 for all tokens.  out = x @ [sb_wq|sb_ww|p_win] + bias
// grid = 512 CTAs (16 tokens each), 512 threads (one output column each)
// ---------------------------------------------------------------------------
__global__ __launch_bounds__(512) void k_pre(
    const float* __restrict__ x,
    const float* __restrict__ sb_wq, const float* __restrict__ sb_bq,
    const float* __restrict__ sb_ww, const float* __restrict__ sb_bw,
    const float* __restrict__ p_win, const float* __restrict__ p_bin)
{
    __shared__ float xs[16 * 512];
    const int t0 = blockIdx.x * 16;
    const int tid = threadIdx.x;
    const float* xb = x + (size_t)t0 * 512;
    for (int idx = tid; idx < 16 * 512; idx += 512) xs[idx] = xb[idx];
    __syncthreads();

    const int c = tid;
    const float* W; int ld; float bias;
    if (c < 128)      { W = sb_wq + c;        ld = 128; bias = sb_bq[c]; }
    else if (c < 256) { W = sb_ww + (c - 128); ld = 128; bias = sb_bw[c - 128]; }
    else              { W = p_win + (c - 256); ld = 256; bias = p_bin[c - 256]; }

    float acc[16];
#pragma unroll
    for (int t = 0; t < 16; t++) acc[t] = 0.f;
    for (int i = 0; i < 512; i++) {
        float w = W[(size_t)i * ld];
#pragma unroll
        for (int t = 0; t < 16; t++) acc[t] += xs[t * 512 + i] * w;
    }
#pragma unroll
    for (int t = 0; t < 16; t++)
        g_qwx[((size_t)(t0 + t)) * 512 + c] = acc[t] + bias;
}

// ---------------------------------------------------------------------------
// Kernel 2: recurrent core.  grid = 8 CTAs (one per batch), 512 threads.
// Slots in smem; DeltaNet state S (one 64-wide row per thread) in registers.
// ---------------------------------------------------------------------------
__global__ __launch_bounds__(512, 1) void k_rec(
    const float* __restrict__ sb_init,
    const float* __restrict__ sb_wo, const float* __restrict__ sb_bo,
    const float* __restrict__ b_wq,  const float* __restrict__ b_bq,
    const float* __restrict__ b_keys,
    const float* __restrict__ bp_w,  const float* __restrict__ bp_b,
    const float* __restrict__ dn_wqkv, const float* __restrict__ dn_bqkv,
    const float* __restrict__ dn_wbeta, const float* __restrict__ dn_bbeta,
    const float* __restrict__ dn_wo, const float* __restrict__ dn_bo,
    const float* __restrict__ dn_lng, const float* __restrict__ dn_lnb,
    const float* __restrict__ sup_w, const float* __restrict__ sup_b,
    const float* __restrict__ op_w,  const float* __restrict__ op_b)
{
    __shared__ float s_slots[Nv * SDv];            // 8192
    __shared__ float s_part[512];
    __shared__ float s_q[128], s_wr[128], s_xh[256];
    __shared__ float s_abuf[64], s_ebuf[64];
    __shared__ float s_a[64], s_g[64], s_ba[64], s_g2[64];
    __shared__ float s_read[128], s_bq[128], s_bind[128];
    __shared__ float s_so[512];
    __shared__ float s_qkv[768], s_khn[256], s_beta[4], s_inv[4];
    __shared__ float s_o[256];
    __shared__ float s_u[128];
    __shared__ float s_red[32], s_red2[32], s_mv[2];

    const int tid = threadIdx.x;
    const int b = blockIdx.x;
    const float invscale = rsqrtf((float)SDv);     // 1/sqrt(128)

    for (int idx = tid; idx < Nv * SDv; idx += 512) s_slots[idx] = sb_init[idx];

    // Register-resident DeltaNet state: thread owns row (l_own, h_own, i_own)
    float Sreg[64];
#pragma unroll
    for (int j = 0; j < 64; j++) Sreg[j] = 0.f;
    const int l_own = tid >> 8;          // 0..1
    const int h_own = (tid >> 6) & 3;    // 0..3
    const int i_own = tid & 63;          // 0..63
    const int wp = tid >> 5, la = tid & 31;
    __syncthreads();

    for (int s = 0; s < Sv; ++s) {
        // --- load precomputed q / wr / xh0 ---
        const float* qwx = g_qwx + ((size_t)(b * Sv + s)) * 512;
        if (tid < 128) s_q[tid] = qwx[tid];
        else if (tid < 256) s_wr[tid - 128] = qwx[tid];
        else s_xh[tid - 256] = qwx[tid];
        __syncthreads();

        // --- attn1 logits: warp w handles slots n = 4w..4w+3 (conflict-free) ---
#pragma unroll
        for (int r = 0; r < 4; r++) {
            int n = wp * 4 + r;
            const float* row = s_slots + n * 128;
            float p = row[la] * s_q[la] + row[la + 32] * s_q[la + 32]
                    + row[la + 64] * s_q[la + 64] + row[la + 96] * s_q[la + 96];
#pragma unroll
            for (int o = 16; o > 0; o >>= 1) p += __shfl_xor_sync(0xffffffffu, p, o);
            if (la == 0) s_abuf[n] = p * invscale;
        }
        __syncthreads();
        if (tid < 64) {
            float m = -1e30f;
            for (int k = 0; k < 64; k++) m = fmaxf(m, s_abuf[k]);
            s_ebuf[tid] = expf(s_abuf[tid] - m);
        }
        __syncthreads();
        if (tid < 64) {
            float sum = 0.f;
            for (int k = 0; k < 64; k++) sum += s_ebuf[k];
            float av = s_ebuf[tid] / sum;
            s_a[tid] = av;
            s_g[tid] = 1.f / (1.f + expf(-av));
        }
        __syncthreads();

        // --- read = a @ slots (partials over n-chunks) ---
        {
            int d = tid & 127, ch = tid >> 7;
            float p = 0.f;
#pragma unroll
            for (int k = 0; k < 16; k++) { int n = ch * 16 + k; p += s_a[n] * s_slots[n * 128 + d]; }
            s_part[ch * 128 + d] = p;
        }
        __syncthreads();
        if (tid < 128)
            s_read[tid] = s_part[tid] + s_part[128 + tid] + s_part[256 + tid] + s_part[384 + tid];
        // slot update #1 (read partials already captured)
        for (int idx = tid; idx < Nv * SDv; idx += 512) {
            int n = idx >> 7, d = idx & 127;
            float g = s_g[n];
            s_slots[idx] = (1.f - g) * s_slots[idx] + g * (s_a[n] * s_wr[d]);
        }
        __syncthreads();

        // --- slot_out = read @ sb_wo + sb_bo  (col per thread), and bq partials ---
        {
            float acc = sb_bo[tid];
            const float* w = sb_wo + tid;
            for (int i = 0; i < 128; i++) acc += s_read[i] * w[(size_t)i * 512];
            s_so[tid] = acc;
        }
        {
            int c = tid & 127, ch = tid >> 7;
            float p = 0.f;
            for (int k = 0; k < 64; k++) { int i = ch * 64 + k; p += s_xh[i] * b_wq[i * 128 + c]; }
            s_part[ch * 128 + c] = p;
        }
        __syncthreads();
        if (tid < 128)
            s_bq[tid] = s_part[tid] + s_part[128 + tid] + s_part[256 + tid] + s_part[384 + tid] + b_bq[tid];
        __syncthreads();

        // --- attn2 logits over b_keys ---
#pragma unroll
        for (int r = 0; r < 4; r++) {
            int n = wp * 4 + r;
            const float* row = b_keys + n * 128;
            float p = row[la] * s_bq[la] + row[la + 32] * s_bq[la + 32]
                    + row[la + 64] * s_bq[la + 64] + row[la + 96] * s_bq[la + 96];
#pragma unroll
            for (int o = 16; o > 0; o >>= 1) p += __shfl_xor_sync(0xffffffffu, p, o);
            if (la == 0) s_abuf[n] = p * invscale;
        }
        __syncthreads();
        if (tid < 64) {
            float m = -1e30f;
            for (int k = 0; k < 64; k++) m = fmaxf(m, s_abuf[k]);
            s_ebuf[tid] = expf(s_abuf[tid] - m);
        }
        __syncthreads();
        if (tid < 64) {
            float sum = 0.f;
            for (int k = 0; k < 64; k++) sum += s_ebuf[k];
            float av = s_ebuf[tid] / sum;
            s_ba[tid] = av;
            s_g2[tid] = 1.f / (1.f + expf(-av));
        }
        __syncthreads();

        // --- bindings = ba @ slots (updated slots) ---
        {
            int d = tid & 127, ch = tid >> 7;
            float p = 0.f;
#pragma unroll
            for (int k = 0; k < 16; k++) { int n = ch * 16 + k; p += s_ba[n] * s_slots[n * 128 + d]; }
            s_part[ch * 128 + d] = p;
        }
        __syncthreads();
        if (tid < 128)
            s_bind[tid] = s_part[tid] + s_part[128 + tid] + s_part[256 + tid] + s_part[384 + tid];
        __syncthreads();

        // --- xh += bindings @ bp_w + bp_b ---
        {
            int c = tid & 255, ch = tid >> 8;
            float p = 0.f;
            for (int k = 0; k < 64; k++) { int i = ch * 64 + k; p += s_bind[i] * bp_w[i * 256 + c]; }
            s_part[ch * 256 + c] = p;
        }
        __syncthreads();
        if (tid < 256) s_xh[tid] += s_part[tid] + s_part[256 + tid] + bp_b[tid];
        __syncthreads();

        // --- DeltaNet layers ---
#pragma unroll
        for (int l = 0; l < 2; l++) {
            const float* Wqkv = dn_wqkv + (size_t)l * 256 * 768;
            const float* bqkv = dn_bqkv + l * 768;
            {
                float a1 = bqkv[tid];
                float a2 = (tid < 256) ? bqkv[tid + 512] : 0.f;
                for (int i = 0; i < 256; i++) {
                    float xv = s_xh[i];
                    const float* row = Wqkv + (size_t)i * 768;
                    a1 += xv * row[tid];
                    if (tid < 256) a2 += xv * row[tid + 512];
                }
                s_qkv[tid] = a1;
                if (tid < 256) s_qkv[tid + 512] = a2;
            }
            if (tid >= 508) {   // beta columns (4)
                int c = tid - 508;
                float acc = dn_bbeta[l * 4 + c];
                const float* wb = dn_wbeta + (size_t)l * 256 * 4;
                for (int i = 0; i < 256; i++) acc += s_xh[i] * wb[i * 4 + c];
                s_beta[c] = 1.f / (1.f + expf(-acc));
            }
            __syncthreads();
            // k-norm
            if (tid < 256) { float k = s_qkv[256 + tid]; s_part[tid] = k * k; }
            __syncthreads();
            if (tid < 4) {
                float ssum = 0.f;
                for (int j = 0; j < 64; j++) ssum += s_part[tid * 64 + j];
                s_inv[tid] = 1.f / (sqrtf(ssum) + 1e-6f);
            }
            __syncthreads();
            if (tid < 256) s_khn[tid] = s_qkv[256 + tid] * s_inv[tid >> 6];
            __syncthreads();
            // register-resident state ops (owners of this layer only)
            if (l_own == l) {
                const float* kh = s_khn + h_own * 64;
                const float* qh = s_qkv + h_own * 64;
                float sk = 0.f;
#pragma unroll
                for (int j = 0; j < 64; j++) sk += Sreg[j] * kh[j];
                float delta = s_beta[h_own] * (s_qkv[512 + h_own * 64 + i_own] - sk);
                float oacc = 0.f;
#pragma unroll
                for (int j = 0; j < 64; j++) { Sreg[j] += delta * kh[j]; oacc += Sreg[j] * qh[j]; }
                s_o[h_own * 64 + i_own] = oacc;
            }
            __syncthreads();
            // o @ dn_wo + bo, residual + LN
            {
                int c = tid & 255, ch = tid >> 8;
                const float* Wo = dn_wo + (size_t)l * 256 * 256;
                float p = 0.f;
                for (int k = 0; k < 128; k++) { int i = ch * 128 + k; p += s_o[i] * Wo[i * 256 + c]; }
                s_part[ch * 256 + c] = p;
            }
            __syncthreads();
            if (tid < 256) {
                float r = s_xh[tid] + s_part[tid] + s_part[256 + tid] + dn_bo[l * 256 + tid];
                s_part[tid] = r;     // reuse lower half (only [256,512) still read above)
            }
            __syncthreads();
            if (tid < 32) {
                float s1 = 0.f, s2 = 0.f;
#pragma unroll
                for (int k = 0; k < 8; k++) { float v = s_part[tid * 8 + k]; s1 += v; s2 += v * v; }
                s_red[tid] = s1; s_red2[tid] = s2;
            }
            __syncthreads();
            if (tid == 0) {
                float s1 = 0.f, s2 = 0.f;
                for (int k = 0; k < 32; k++) { s1 += s_red[k]; s2 += s_red2[k]; }
                float m = s1 / 256.f;
                float var = s2 / 256.f - m * m;
                s_mv[0] = m; s_mv[1] = rsqrtf(var + 1e-5f);
            }
            __syncthreads();
            if (tid < 256)
                s_xh[tid] = (s_part[tid] - s_mv[0]) * s_mv[1] * dn_lng[l * 256 + tid] + dn_lnb[l * 256 + tid];
            __syncthreads();
        }

        // --- output column + u = xh @ sup_w ---
        float y_acc = op_b[tid];
        {
            const float* w = op_w + tid;
            for (int i = 0; i < 256; i++) y_acc += s_xh[i] * w[(size_t)i * 512];
        }
        {
            int c = tid & 127, ch = tid >> 7;
            float p = 0.f;
            for (int k = 0; k < 64; k++) { int i = ch * 64 + k; p += s_xh[i] * sup_w[i * 128 + c]; }
            s_part[ch * 128 + c] = p;
        }
        g_ypre[((size_t)(b * Sv + s)) * 512 + tid] = s_so[tid] + y_acc;
        __syncthreads();
        if (tid < 128)
            s_u[tid] = s_part[tid] + s_part[128 + tid] + s_part[256 + tid] + s_part[384 + tid];
        __syncthreads();
        // slot update #2
        for (int idx = tid; idx < Nv * SDv; idx += 512) {
            int n = idx >> 7, d = idx & 127;
            float g = s_g2[n];
            s_slots[idx] = (1.f - g) * s_slots[idx] + g * (s_ba[n] * s_u[d] + sup_b[d]);
        }
        __syncthreads();
    }
}

// ---------------------------------------------------------------------------
// Kernel 3: out = LN(ypre) @ ow + ob.  grid = 512 CTAs x 16 tokens.
// ---------------------------------------------------------------------------
__global__ __launch_bounds__(512) void k_out(
    const float* __restrict__ oln_g, const float* __restrict__ oln_b,
    const float* __restrict__ ow, const float* __restrict__ ob,
    float* __restrict__ out)
{
    __shared__ float yt[16 * 512];
    __shared__ float mv[16][2];
    const int t0 = blockIdx.x * 16;
    const int tid = threadIdx.x;
    const float* src = g_ypre + (size_t)t0 * 512;
    for (int idx = tid; idx < 16 * 512; idx += 512) yt[idx] = src[idx];
    __syncthreads();
    {
        int tt = tid >> 5, lane = tid & 31;
        float s1 = 0.f, s2 = 0.f;
        for (int i = lane; i < 512; i += 32) { float v = yt[tt * 512 + i]; s1 += v; s2 += v * v; }
#pragma unroll
        for (int o = 16; o > 0; o >>= 1) {
            s1 += __shfl_xor_sync(0xffffffffu, s1, o);
            s2 += __shfl_xor_sync(0xffffffffu, s2, o);
        }
        if (lane == 0) {
            float m = s1 / 512.f;
            mv[tt][0] = m;
            mv[tt][1] = rsqrtf(s2 / 512.f - m * m + 1e-5f);
        }
    }
    __syncthreads();
    for (int idx = tid; idx < 16 * 512; idx += 512) {
        int tt = idx >> 9, c = idx & 511;
        yt[idx] = (yt[idx] - mv[tt][0]) * mv[tt][1] * oln_g[c] + oln_b[c];
    }
    __syncthreads();
    float acc[16];
#pragma unroll
    for (int t = 0; t < 16; t++) acc[t] = ob[tid];
    const float* w = ow + tid;
    for (int i = 0; i < 512; i++) {
        float wv = w[(size_t)i * 512];
#pragma unroll
        for (int t = 0; t < 16; t++) acc[t] += yt[t * 512 + i] * wv;
    }
    float* dst = out + (size_t)t0 * 512;
#pragma unroll
    for (int t = 0; t < 16; t++) dst[t * 512 + tid] = acc[t];
}

// ---------------------------------------------------------------------------
extern "C" void kernel_launch(void* const* d_in, const int* in_sizes, int n_in,
                              void* d_out, int out_size)
{
    const float* x        = (const float*)d_in[0];
    const float* sb_init  = (const float*)d_in[1];
    const float* sb_wq    = (const float*)d_in[2];
    const float* sb_bq    = (const float*)d_in[3];
    const float* sb_ww    = (const float*)d_in[4];
    const float* sb_bw    = (const float*)d_in[5];
    const float* sb_wo    = (const float*)d_in[6];
    const float* sb_bo    = (const float*)d_in[7];
    const float* p_win    = (const float*)d_in[8];
    const float* p_bin    = (const float*)d_in[9];
    const float* b_wq     = (const float*)d_in[10];
    const float* b_bq     = (const float*)d_in[11];
    const float* b_keys   = (const float*)d_in[12];
    const float* bp_w     = (const float*)d_in[13];
    const float* bp_b     = (const float*)d_in[14];
    const float* dn_wqkv  = (const float*)d_in[15];
    const float* dn_bqkv  = (const float*)d_in[16];
    const float* dn_wbeta = (const float*)d_in[17];
    const float* dn_bbeta = (const float*)d_in[18];
    const float* dn_wo    = (const float*)d_in[19];
    const float* dn_bo    = (const float*)d_in[20];
    const float* dn_lng   = (const float*)d_in[21];
    const float* dn_lnb   = (const float*)d_in[22];
    const float* sup_w    = (const float*)d_in[23];
    const float* sup_b    = (const float*)d_in[24];
    const float* op_w     = (const float*)d_in[25];
    const float* op_b     = (const float*)d_in[26];
    const float* oln_g    = (const float*)d_in[27];
    const float* oln_b    = (const float*)d_in[28];
    const float* ow       = (const float*)d_in[29];
    const float* ob       = (const float*)d_in[30];

    k_pre<<<512, 512>>>(x, sb_wq, sb_bq, sb_ww, sb_bw, p_win, p_bin);
    k_rec<<<8, 512>>>(sb_init, sb_wo, sb_bo, b_wq, b_bq, b_keys, bp_w, bp_b,
                      dn_wqkv, dn_bqkv, dn_wbeta, dn_bbeta, dn_wo, dn_bo,
                      dn_lng, dn_lnb, sup_w, sup_b, op_w, op_b);
    k_out<<<512, 512>>>(oln_g, oln_b, ow, ob, (float*)d_out);
}

// round 3
// speedup vs baseline: 2.4656x; 2.4656x over previous
#include <cuda_runtime.h>
#include <cuda_fp16.h>
#include <math.h>

#define Bv 8
#define Sv 1024
#define Dv 512
#define Hv 256
#define Nv 64
#define SDv 128
#define NHv 4
#define DHv 64

// ---- device scratch (no allocations allowed) ----
__device__ float g_qwx[(size_t)Bv * Sv * 512];   // per token: [q(128) | wr(128) | xh0(256)]
__device__ float g_ba[(size_t)Bv * Sv * 64];     // precomputed attn2 softmax
__device__ float g_rx[(size_t)Bv * Sv * 384];    // per token: [read(128) | xh_final(256)]
__device__ __half g_h[591872];                   // fp16 weight pack

#define H_QKV   0          // 2*256*768 = 393216
#define H_WO    393216     // 2*256*256 = 131072
#define H_BPW   524288     // 128*256   = 32768
#define H_SUPW  557056     // 256*128   = 32768
#define H_WBETA 589824     // 2*256*4   = 2048
#define H_TOTAL 591872

// ---------------------------------------------------------------------------
// Convert recurrent weights to fp16 pack
// ---------------------------------------------------------------------------
__global__ __launch_bounds__(512) void k_cvt(
    const float* __restrict__ wqkv, const float* __restrict__ wo,
    const float* __restrict__ bpw, const float* __restrict__ supw,
    const float* __restrict__ wbeta)
{
    int i = blockIdx.x * 512 + threadIdx.x;
    if (i >= H_TOTAL) return;
    float v;
    if (i < H_WO)        v = wqkv[i];
    else if (i < H_BPW)  v = wo[i - H_WO];
    else if (i < H_SUPW) v = bpw[i - H_BPW];
    else if (i < H_WBETA) v = supw[i - H_SUPW];
    else                 v = wbeta[i - H_WBETA];
    g_h[i] = __float2half(v);
}

// ---------------------------------------------------------------------------
// Kernel 1: q/wr/xh0 for all tokens. 16 tokens per CTA, 512 cols.
// ---------------------------------------------------------------------------
__global__ __launch_bounds__(512) void k_pre(
    const float* __restrict__ x,
    const float* __restrict__ sb_wq, const float* __restrict__ sb_bq,
    const float* __restrict__ sb_ww, const float* __restrict__ sb_bw,
    const float* __restrict__ p_win, const float* __restrict__ p_bin)
{
    __shared__ float xs[16 * 512];
    const int t0 = blockIdx.x * 16;
    const int tid = threadIdx.x;
    const float* xb = x + (size_t)t0 * 512;
    for (int idx = tid; idx < 16 * 512; idx += 512) xs[idx] = xb[idx];
    __syncthreads();

    const int c = tid;
    const float* W; int ld; float bias;
    if (c < 128)      { W = sb_wq + c;         ld = 128; bias = sb_bq[c]; }
    else if (c < 256) { W = sb_ww + (c - 128); ld = 128; bias = sb_bw[c - 128]; }
    else              { W = p_win + (c - 256); ld = 256; bias = p_bin[c - 256]; }

    float acc[16];
#pragma unroll
    for (int t = 0; t < 16; t++) acc[t] = 0.f;
    for (int i = 0; i < 512; i++) {
        float w = W[(size_t)i * ld];
#pragma unroll
        for (int t = 0; t < 16; t++) acc[t] += xs[t * 512 + i] * w;
    }
#pragma unroll
    for (int t = 0; t < 16; t++)
        g_qwx[((size_t)(t0 + t)) * 512 + c] = acc[t] + bias;
}

// ---------------------------------------------------------------------------
// Kernel 1b: precompute ba = softmax( (xh0 @ b_wq + b_bq) @ b_keys^T / scale )
// 8 tokens per CTA of 256 threads.
// ---------------------------------------------------------------------------
__global__ __launch_bounds__(256) void k_ba(
    const float* __restrict__ b_wq, const float* __restrict__ b_bq,
    const float* __restrict__ b_keys)
{
    __shared__ float s_x[8 * 256];
    __shared__ float s_keys[64 * 129];
    __shared__ float s_bq[8 * 128];
    const int t0 = blockIdx.x * 8;
    const int tid = threadIdx.x;

    for (int idx = tid; idx < 8 * 256; idx += 256) {
        int t = idx >> 8, i = idx & 255;
        s_x[idx] = g_qwx[((size_t)(t0 + t)) * 512 + 256 + i];
    }
    for (int idx = tid; idx < 64 * 128; idx += 256) {
        int n = idx >> 7, k = idx & 127;
        s_keys[n * 129 + k] = b_keys[idx];
    }
    __syncthreads();

    // bq = xh0 @ b_wq + b_bq  (thread: col c, token group of 4)
    {
        int c = tid & 127, tg = tid >> 7;  // tg in {0,1}
        float acc[4];
        float bb = b_bq[c];
#pragma unroll
        for (int t = 0; t < 4; t++) acc[t] = bb;
        for (int i = 0; i < 256; i++) {
            float w = b_wq[i * 128 + c];
#pragma unroll
            for (int t = 0; t < 4; t++) acc[t] += s_x[(tg * 4 + t) * 256 + i] * w;
        }
#pragma unroll
        for (int t = 0; t < 4; t++) s_bq[(tg * 4 + t) * 128 + c] = acc[t];
    }
    __syncthreads();

    // logits + softmax: warp per token, 2 slots per lane
    {
        const float invscale = 0.08838834764831845f;  // 1/sqrt(128)
        int t = tid >> 5, lane = tid & 31;
        float l0 = 0.f, l1 = 0.f;
        for (int k = 0; k < 128; k++) {
            float q = s_bq[t * 128 + k];
            l0 += q * s_keys[lane * 129 + k];
            l1 += q * s_keys[(lane + 32) * 129 + k];
        }
        l0 *= invscale; l1 *= invscale;
        float m = fmaxf(l0, l1);
#pragma unroll
        for (int o = 16; o > 0; o >>= 1) m = fmaxf(m, __shfl_xor_sync(0xffffffffu, m, o));
        float e0 = expf(l0 - m), e1 = expf(l1 - m);
        float ssum = e0 + e1;
#pragma unroll
        for (int o = 16; o > 0; o >>= 1) ssum += __shfl_xor_sync(0xffffffffu, ssum, o);
        float inv = 1.f / ssum;
        float* dst = g_ba + ((size_t)(t0 + t)) * 64;
        dst[lane] = e0 * inv;
        dst[lane + 32] = e1 * inv;
    }
}

// ---------------------------------------------------------------------------
// Kernel 2: recurrent core. 8 CTAs, 512 threads, dynamic smem.
// ---------------------------------------------------------------------------
__global__ __launch_bounds__(512, 1) void k_rec(
    const float* __restrict__ sb_init, const float* __restrict__ bp_b,
    const float* __restrict__ dn_bqkv, const float* __restrict__ dn_bbeta,
    const float* __restrict__ dn_bo, const float* __restrict__ dn_lng,
    const float* __restrict__ dn_lnb, const float* __restrict__ sup_b)
{
    extern __shared__ float sm[];
    float* s_slots = sm;               // 8192
    float* s_part  = sm + 8192;        // 4096
    float* s_bqkv  = sm + 12288;       // 1536
    float* s_bo    = sm + 13824;       // 512
    float* s_lng   = sm + 14336;       // 512
    float* s_lnb   = sm + 14848;       // 512
    float* s_bpb   = sm + 15360;       // 256
    float* s_supb  = sm + 15616;       // 128
    float* s_bbeta = sm + 15744;       // 8
    float* s_q     = sm + 15752;       // 128
    float* s_wr    = sm + 15880;       // 128
    float* s_xh    = sm + 16008;       // 256
    float* s_abuf  = sm + 16264;       // 64
    float* s_ebuf  = sm + 16328;       // 64
    float* s_a     = sm + 16392;       // 64
    float* s_g     = sm + 16456;       // 64
    float* s_ba    = sm + 16520;       // 64
    float* s_g2    = sm + 16584;       // 64
    float* s_read  = sm + 16648;       // 128
    float* s_bind  = sm + 16776;       // 128
    float* s_qkv   = sm + 16904;       // 768
    float* s_khn   = sm + 17672;       // 256
    float* s_beta  = sm + 17928;       // 4
    float* s_inv   = sm + 17932;       // 4
    float* s_o     = sm + 17936;       // 256
    float* s_resid = sm + 18192;       // 256
    float* s_u     = sm + 18448;       // 128
    float* s_red   = sm + 18576;       // 32
    float* s_red2  = sm + 18608;       // 32
    float* s_mv    = sm + 18640;       // 2

    const int tid = threadIdx.x;
    const int b = blockIdx.x;
    const float invscale = 0.08838834764831845f;

    for (int idx = tid; idx < Nv * SDv; idx += 512) s_slots[idx] = sb_init[idx];
    for (int i = tid; i < 1536; i += 512) s_bqkv[i] = dn_bqkv[i];
    if (tid < 512) { s_bo[tid] = dn_bo[tid]; s_lng[tid] = dn_lng[tid]; s_lnb[tid] = dn_lnb[tid]; }
    if (tid < 256) s_bpb[tid] = bp_b[tid];
    if (tid < 128) s_supb[tid] = sup_b[tid];
    if (tid < 8) s_bbeta[tid] = dn_bbeta[tid];

    float Sreg[64];
#pragma unroll
    for (int j = 0; j < 64; j++) Sreg[j] = 0.f;
    const int l_own = tid >> 8;
    const int h_own = (tid >> 6) & 3;
    const int i_own = tid & 63;
    const int wp = tid >> 5, la = tid & 31;
    __syncthreads();

    for (int s = 0; s < Sv; ++s) {
        const size_t tok = (size_t)(b * Sv + s);
        // --- load precomputed q / wr / xh0 / ba ---
        const float* qwx = g_qwx + tok * 512;
        if (tid < 128) s_q[tid] = qwx[tid];
        else if (tid < 256) s_wr[tid - 128] = qwx[tid];
        else s_xh[tid - 256] = qwx[tid];
        if (tid < 64) {
            float v = g_ba[tok * 64 + tid];
            s_ba[tid] = v;
            s_g2[tid] = 1.f / (1.f + expf(-v));
        }
        __syncthreads();

        // --- attn1 logits (warp per 4 slots, shfl reduce) ---
#pragma unroll
        for (int r = 0; r < 4; r++) {
            int n = wp * 4 + r;
            const float* row = s_slots + n * 128;
            float p = row[la] * s_q[la] + row[la + 32] * s_q[la + 32]
                    + row[la + 64] * s_q[la + 64] + row[la + 96] * s_q[la + 96];
#pragma unroll
            for (int o = 16; o > 0; o >>= 1) p += __shfl_xor_sync(0xffffffffu, p, o);
            if (la == 0) s_abuf[n] = p * invscale;
        }
        __syncthreads();
        if (tid < 64) {
            float m = -1e30f;
            for (int k = 0; k < 64; k++) m = fmaxf(m, s_abuf[k]);
            s_ebuf[tid] = expf(s_abuf[tid] - m);
        }
        __syncthreads();
        if (tid < 64) {
            float sum = 0.f;
            for (int k = 0; k < 64; k++) sum += s_ebuf[k];
            float av = s_ebuf[tid] / sum;
            s_a[tid] = av;
            s_g[tid] = 1.f / (1.f + expf(-av));
        }
        __syncthreads();

        // --- read = a @ slots (partials) ---
        {
            int d = tid & 127, ch = tid >> 7;
            float p = 0.f;
#pragma unroll
            for (int k = 0; k < 16; k++) { int n = ch * 16 + k; p += s_a[n] * s_slots[n * 128 + d]; }
            s_part[ch * 128 + d] = p;
        }
        __syncthreads();
        if (tid < 128) {
            float rv = s_part[tid] + s_part[128 + tid] + s_part[256 + tid] + s_part[384 + tid];
            s_read[tid] = rv;
            g_rx[tok * 384 + tid] = rv;     // export for epilogue
        }
        // slot update #1
        for (int idx = tid; idx < Nv * SDv; idx += 512) {
            int n = idx >> 7, d = idx & 127;
            float g = s_g[n];
            s_slots[idx] = (1.f - g) * s_slots[idx] + g * (s_a[n] * s_wr[d]);
        }
        __syncthreads();

        // --- bindings = ba @ slots (updated) ---
        {
            int d = tid & 127, ch = tid >> 7;
            float p = 0.f;
#pragma unroll
            for (int k = 0; k < 16; k++) { int n = ch * 16 + k; p += s_ba[n] * s_slots[n * 128 + d]; }
            s_part[ch * 128 + d] = p;
        }
        __syncthreads();
        if (tid < 128)
            s_bind[tid] = s_part[tid] + s_part[128 + tid] + s_part[256 + tid] + s_part[384 + tid];
        __syncthreads();

        // --- xh += bindings @ bp_w + bp_b  (fp16 vec8: 32 colgroups x 16 isegs) ---
        {
            int cg = tid & 31, iseg = tid >> 5;           // rows/seg = 8
            const uint4* W = ((const uint4*)(g_h + H_BPW)) + (size_t)iseg * 8 * 32 + cg;
            float a0=0,a1=0,a2=0,a3=0,a4=0,a5=0,a6=0,a7=0;
#pragma unroll
            for (int r = 0; r < 8; r++) {
                float xv = s_bind[iseg * 8 + r];
                uint4 w = W[(size_t)r * 32];
                half2 h0 = *(half2*)&w.x, h1 = *(half2*)&w.y, h2 = *(half2*)&w.z, h3 = *(half2*)&w.w;
                a0 += xv * __low2float(h0); a1 += xv * __high2float(h0);
                a2 += xv * __low2float(h1); a3 += xv * __high2float(h1);
                a4 += xv * __low2float(h2); a5 += xv * __high2float(h2);
                a6 += xv * __low2float(h3); a7 += xv * __high2float(h3);
            }
            float* P = s_part + iseg * 256 + cg * 8;
            P[0]=a0; P[1]=a1; P[2]=a2; P[3]=a3; P[4]=a4; P[5]=a5; P[6]=a6; P[7]=a7;
        }
        __syncthreads();
        if (tid < 256) {
            float p = s_bpb[tid];
            for (int sg = 0; sg < 16; sg++) p += s_part[sg * 256 + tid];
            s_xh[tid] += p;
        }
        __syncthreads();

        // --- DeltaNet layers ---
#pragma unroll
        for (int l = 0; l < 2; l++) {
            // qkv GEMV (fp16 vec8: 96 colgroups x 4 isegs, threads 0-383) + beta (warps 12-15)
            if (tid < 384) {
                int cg = tid % 96, iseg = tid / 96;       // rows/seg = 64
                const uint4* W = ((const uint4*)(g_h + H_QKV)) + (size_t)l * 24576
                               + (size_t)iseg * 64 * 96 + cg;
                float a0=0,a1=0,a2=0,a3=0,a4=0,a5=0,a6=0,a7=0;
#pragma unroll 8
                for (int r = 0; r < 64; r++) {
                    float xv = s_xh[iseg * 64 + r];
                    uint4 w = W[(size_t)r * 96];
                    half2 h0 = *(half2*)&w.x, h1 = *(half2*)&w.y, h2 = *(half2*)&w.z, h3 = *(half2*)&w.w;
                    a0 += xv * __low2float(h0); a1 += xv * __high2float(h0);
                    a2 += xv * __low2float(h1); a3 += xv * __high2float(h1);
                    a4 += xv * __low2float(h2); a5 += xv * __high2float(h2);
                    a6 += xv * __low2float(h3); a7 += xv * __high2float(h3);
                }
                float* P = s_part + iseg * 768 + cg * 8;
                P[0]=a0; P[1]=a1; P[2]=a2; P[3]=a3; P[4]=a4; P[5]=a5; P[6]=a6; P[7]=a7;
            } else {
                int c = (tid >> 5) - 12;
                float acc = 0.f;
                const __half* Wb = g_h + H_WBETA + (size_t)l * 1024;
#pragma unroll
                for (int k = 0; k < 8; k++) {
                    int i = k * 32 + la;
                    acc += s_xh[i] * __half2float(Wb[i * 4 + c]);
                }
#pragma unroll
                for (int o = 16; o > 0; o >>= 1) acc += __shfl_xor_sync(0xffffffffu, acc, o);
                if (la == 0) {
                    float z = acc + s_bbeta[l * 4 + c];
                    s_beta[c] = 1.f / (1.f + expf(-z));
                }
            }
            __syncthreads();
            // reduce qkv partials + bias
            {
                float v = s_bqkv[l * 768 + tid]
                        + s_part[tid] + s_part[768 + tid] + s_part[1536 + tid] + s_part[2304 + tid];
                s_qkv[tid] = v;
                if (tid < 256) {
                    int c = 512 + tid;
                    float v2 = s_bqkv[l * 768 + c]
                             + s_part[c] + s_part[768 + c] + s_part[1536 + c] + s_part[2304 + c];
                    s_qkv[c] = v2;
                }
            }
            __syncthreads();
            // k-norm
            if (tid < 256) { float k = s_qkv[256 + tid]; s_part[tid] = k * k; }
            __syncthreads();
            if (tid < 4) {
                float ssum = 0.f;
                for (int j = 0; j < 64; j++) ssum += s_part[tid * 64 + j];
                s_inv[tid] = 1.f / (sqrtf(ssum) + 1e-6f);
            }
            __syncthreads();
            if (tid < 256) s_khn[tid] = s_qkv[256 + tid] * s_inv[tid >> 6];
            __syncthreads();
            // register-resident state update
            if (l_own == l) {
                const float* kh = s_khn + h_own * 64;
                const float* qh = s_qkv + h_own * 64;
                float sk = 0.f;
#pragma unroll
                for (int j = 0; j < 64; j++) sk += Sreg[j] * kh[j];
                float delta = s_beta[h_own] * (s_qkv[512 + h_own * 64 + i_own] - sk);
                float oacc = 0.f;
#pragma unroll
                for (int j = 0; j < 64; j++) { Sreg[j] += delta * kh[j]; oacc += Sreg[j] * qh[j]; }
                s_o[h_own * 64 + i_own] = oacc;
            }
            __syncthreads();
            // o @ dn_wo (fp16 vec8: 32 colgroups x 16 isegs)
            {
                int cg = tid & 31, iseg = tid >> 5;       // rows/seg = 16
                const uint4* W = ((const uint4*)(g_h + H_WO)) + (size_t)l * 8192
                               + (size_t)iseg * 16 * 32 + cg;
                float a0=0,a1=0,a2=0,a3=0,a4=0,a5=0,a6=0,a7=0;
#pragma unroll
                for (int r = 0; r < 16; r++) {
                    float xv = s_o[iseg * 16 + r];
                    uint4 w = W[(size_t)r * 32];
                    half2 h0 = *(half2*)&w.x, h1 = *(half2*)&w.y, h2 = *(half2*)&w.z, h3 = *(half2*)&w.w;
                    a0 += xv * __low2float(h0); a1 += xv * __high2float(h0);
                    a2 += xv * __low2float(h1); a3 += xv * __high2float(h1);
                    a4 += xv * __low2float(h2); a5 += xv * __high2float(h2);
                    a6 += xv * __low2float(h3); a7 += xv * __high2float(h3);
                }
                float* P = s_part + iseg * 256 + cg * 8;
                P[0]=a0; P[1]=a1; P[2]=a2; P[3]=a3; P[4]=a4; P[5]=a5; P[6]=a6; P[7]=a7;
            }
            __syncthreads();
            if (tid < 256) {
                float p = s_bo[l * 256 + tid];
                for (int sg = 0; sg < 16; sg++) p += s_part[sg * 256 + tid];
                s_resid[tid] = s_xh[tid] + p;
            }
            __syncthreads();
            // LayerNorm
            if (tid < 32) {
                float s1 = 0.f, s2 = 0.f;
#pragma unroll
                for (int k = 0; k < 8; k++) { float v = s_resid[tid * 8 + k]; s1 += v; s2 += v * v; }
                s_red[tid] = s1; s_red2[tid] = s2;
            }
            __syncthreads();
            if (tid == 0) {
                float s1 = 0.f, s2 = 0.f;
                for (int k = 0; k < 32; k++) { s1 += s_red[k]; s2 += s_red2[k]; }
                float m = s1 / 256.f;
                float var = s2 / 256.f - m * m;
                s_mv[0] = m; s_mv[1] = rsqrtf(var + 1e-5f);
            }
            __syncthreads();
            if (tid < 256)
                s_xh[tid] = (s_resid[tid] - s_mv[0]) * s_mv[1] * s_lng[l * 256 + tid] + s_lnb[l * 256 + tid];
            __syncthreads();
        }

        // --- u = xh @ sup_w (fp16 vec8: 16 colgroups x 32 isegs), export xh ---
        {
            int cg = tid & 15, iseg = tid >> 4;           // rows/seg = 8
            const uint4* W = ((const uint4*)(g_h + H_SUPW)) + (size_t)iseg * 8 * 16 + cg;
            float a0=0,a1=0,a2=0,a3=0,a4=0,a5=0,a6=0,a7=0;
#pragma unroll
            for (int r = 0; r < 8; r++) {
                float xv = s_xh[iseg * 8 + r];
                uint4 w = W[(size_t)r * 16];
                half2 h0 = *(half2*)&w.x, h1 = *(half2*)&w.y, h2 = *(half2*)&w.z, h3 = *(half2*)&w.w;
                a0 += xv * __low2float(h0); a1 += xv * __high2float(h0);
                a2 += xv * __low2float(h1); a3 += xv * __high2float(h1);
                a4 += xv * __low2float(h2); a5 += xv * __high2float(h2);
                a6 += xv * __low2float(h3); a7 += xv * __high2float(h3);
            }
            float* P = s_part + iseg * 128 + cg * 8;
            P[0]=a0; P[1]=a1; P[2]=a2; P[3]=a3; P[4]=a4; P[5]=a5; P[6]=a6; P[7]=a7;
        }
        if (tid < 256) g_rx[tok * 384 + 128 + tid] = s_xh[tid];
        __syncthreads();
        if (tid < 128) {
            float p = 0.f;
            for (int sg = 0; sg < 32; sg++) p += s_part[sg * 128 + tid];
            s_u[tid] = p;
        }
        __syncthreads();
        // slot update #2
        for (int idx = tid; idx < Nv * SDv; idx += 512) {
            int n = idx >> 7, d = idx & 127;
            float g = s_g2[n];
            s_slots[idx] = (1.f - g) * s_slots[idx] + g * (s_ba[n] * s_u[d] + s_supb[d]);
        }
        __syncthreads();
    }
}

// ---------------------------------------------------------------------------
// Kernel 3: ypre = read@sb_wo + xh@op_w + biases; out = LN(ypre) @ ow + ob.
// 8 tokens per CTA of 512 threads.
// ---------------------------------------------------------------------------
__global__ __launch_bounds__(512) void k_out(
    const float* __restrict__ sb_wo, const float* __restrict__ sb_bo,
    const float* __restrict__ op_w, const float* __restrict__ op_b,
    const float* __restrict__ oln_g, const float* __restrict__ oln_b,
    const float* __restrict__ ow, const float* __restrict__ ob,
    float* __restrict__ out)
{
    __shared__ float rx[8 * 384];
    __shared__ float yt[8 * 512];
    __shared__ float mv[8][2];
    const int t0 = blockIdx.x * 8;
    const int tid = threadIdx.x;
    const float* src = g_rx + (size_t)t0 * 384;
    for (int idx = tid; idx < 8 * 384; idx += 512) rx[idx] = src[idx];
    __syncthreads();

    // ypre
    {
        float acc[8];
        float bias = sb_bo[tid] + op_b[tid];
#pragma unroll
        for (int t = 0; t < 8; t++) acc[t] = bias;
        const float* w1 = sb_wo + tid;
        for (int i = 0; i < 128; i++) {
            float wv = w1[(size_t)i * 512];
#pragma unroll
            for (int t = 0; t < 8; t++) acc[t] += rx[t * 384 + i] * wv;
        }
        const float* w2 = op_w + tid;
        for (int i = 0; i < 256; i++) {
            float wv = w2[(size_t)i * 512];
#pragma unroll
            for (int t = 0; t < 8; t++) acc[t] += rx[t * 384 + 128 + i] * wv;
        }
#pragma unroll
        for (int t = 0; t < 8; t++) yt[t * 512 + tid] = acc[t];
    }
    __syncthreads();

    // LN stats: warp per token (warps 0-7)
    if (tid < 256) {
        int tt = tid >> 5, lane = tid & 31;
        float s1 = 0.f, s2 = 0.f;
        for (int i = lane; i < 512; i += 32) { float v = yt[tt * 512 + i]; s1 += v; s2 += v * v; }
#pragma unroll
        for (int o = 16; o > 0; o >>= 1) {
            s1 += __shfl_xor_sync(0xffffffffu, s1, o);
            s2 += __shfl_xor_sync(0xffffffffu, s2, o);
        }
        if (lane == 0) {
            float m = s1 / 512.f;
            mv[tt][0] = m;
            mv[tt][1] = rsqrtf(s2 / 512.f - m * m + 1e-5f);
        }
    }
    __syncthreads();
    for (int idx = tid; idx < 8 * 512; idx += 512) {
        int tt = idx >> 9, c = idx & 511;
        yt[idx] = (yt[idx] - mv[tt][0]) * mv[tt][1] * oln_g[c] + oln_b[c];
    }
    __syncthreads();

    float acc[8];
#pragma unroll
    for (int t = 0; t < 8; t++) acc[t] = ob[tid];
    const float* w = ow + tid;
    for (int i = 0; i < 512; i++) {
        float wv = w[(size_t)i * 512];
#pragma unroll
        for (int t = 0; t < 8; t++) acc[t] += yt[t * 512 + i] * wv;
    }
    float* dst = out + (size_t)t0 * 512;
#pragma unroll
    for (int t = 0; t < 8; t++) dst[t * 512 + tid] = acc[t];
}

// ---------------------------------------------------------------------------
extern "C" void kernel_launch(void* const* d_in, const int* in_sizes, int n_in,
                              void* d_out, int out_size)
{
    const float* x        = (const float*)d_in[0];
    const float* sb_init  = (const float*)d_in[1];
    const float* sb_wq    = (const float*)d_in[2];
    const float* sb_bq    = (const float*)d_in[3];
    const float* sb_ww    = (const float*)d_in[4];
    const float* sb_bw    = (const float*)d_in[5];
    const float* sb_wo    = (const float*)d_in[6];
    const float* sb_bo    = (const float*)d_in[7];
    const float* p_win    = (const float*)d_in[8];
    const float* p_bin    = (const float*)d_in[9];
    const float* b_wq     = (const float*)d_in[10];
    const float* b_bq     = (const float*)d_in[11];
    const float* b_keys   = (const float*)d_in[12];
    const float* bp_w     = (const float*)d_in[13];
    const float* bp_b     = (const float*)d_in[14];
    const float* dn_wqkv  = (const float*)d_in[15];
    const float* dn_bqkv  = (const float*)d_in[16];
    const float* dn_wbeta = (const float*)d_in[17];
    const float* dn_bbeta = (const float*)d_in[18];
    const float* dn_wo    = (const float*)d_in[19];
    const float* dn_bo    = (const float*)d_in[20];
    const float* dn_lng   = (const float*)d_in[21];
    const float* dn_lnb   = (const float*)d_in[22];
    const float* sup_w    = (const float*)d_in[23];
    const float* sup_b    = (const float*)d_in[24];
    const float* op_w     = (const float*)d_in[25];
    const float* op_b     = (const float*)d_in[26];
    const float* oln_g    = (const float*)d_in[27];
    const float* oln_b    = (const float*)d_in[28];
    const float* ow       = (const float*)d_in[29];
    const float* ob       = (const float*)d_in[30];

    static bool attr_set = false;
    if (!attr_set) {
        cudaFuncSetAttribute(k_rec, cudaFuncAttributeMaxDynamicSharedMemorySize, 76 * 1024);
        attr_set = true;
    }

    k_cvt<<<(H_TOTAL + 511) / 512, 512>>>(dn_wqkv, dn_wo, bp_w, sup_w, dn_wbeta);
    k_pre<<<512, 512>>>(x, sb_wq, sb_bq, sb_ww, sb_bw, p_win, p_bin);
    k_ba<<<1024, 256>>>(b_wq, b_bq, b_keys);
    k_rec<<<8, 512, 76 * 1024>>>(sb_init, bp_b, dn_bqkv, dn_bbeta, dn_bo,
                                 dn_lng, dn_lnb, sup_b);
    k_out<<<1024, 512>>>(sb_wo, sb_bo, op_w, op_b, oln_g, oln_b, ow, ob, (float*)d_out);
}

// round 5
// speedup vs baseline: 3.2131x; 1.3032x over previous
#include <cuda_runtime.h>
#include <cuda_fp16.h>
#include <cstdint>
#include <math.h>

#define Bv 8
#define Sv 1024
#define Dv 512
#define Hv 256
#define Nv 64
#define SDv 128
#define NHv 4
#define DHv 64

// ---- device scratch (no allocations allowed) ----
__device__ float g_qwx[(size_t)Bv * Sv * 512];   // per token: [q(128) | wr(128) | xh0(256)]
__device__ float g_ba[(size_t)Bv * Sv * 64];     // precomputed attn2 softmax
__device__ float g_rx[(size_t)Bv * Sv * 384];    // per token: [read(128) | xh_final(256)]
__device__ __align__(256) __half g_h[591872];    // fp16 weight pack

#define H_QKV   0          // 2*256*768 = 393216
#define H_WO    393216     // 2*256*256 = 131072
#define H_BPW   524288     // 128*256   = 32768
#define H_SUPW  557056     // 256*128   = 32768
#define H_WBETA 589824     // 2*256*4   = 2048
#define H_TOTAL 591872

// ---- cluster helpers ----
__device__ __forceinline__ void cluster_sync_() {
    asm volatile("barrier.cluster.arrive.aligned;" ::: "memory");
    asm volatile("barrier.cluster.wait.aligned;" ::: "memory");
}
__device__ __forceinline__ void st_cluster_f32(float* p, int rr, float v) {
    unsigned int l = (unsigned int)__cvta_generic_to_shared(p);
    unsigned int r;
    asm volatile("mapa.shared::cluster.u32 %0, %1, %2;" : "=r"(r) : "r"(l), "r"(rr));
    asm volatile("st.shared::cluster.f32 [%0], %1;" :: "r"(r), "f"(v) : "memory");
}

// ---------------------------------------------------------------------------
// Convert recurrent weights to fp16 pack
// ---------------------------------------------------------------------------
__global__ __launch_bounds__(512) void k_cvt(
    const float* __restrict__ wqkv, const float* __restrict__ wo,
    const float* __restrict__ bpw, const float* __restrict__ supw,
    const float* __restrict__ wbeta)
{
    int i = blockIdx.x * 512 + threadIdx.x;
    if (i >= H_TOTAL) return;
    float v;
    if (i < H_WO)        v = wqkv[i];
    else if (i < H_BPW)  v = wo[i - H_WO];
    else if (i < H_SUPW) v = bpw[i - H_BPW];
    else if (i < H_WBETA) v = supw[i - H_SUPW];
    else                 v = wbeta[i - H_WBETA];
    g_h[i] = __float2half(v);
}

// ---------------------------------------------------------------------------
// Kernel 1: q/wr/xh0 for all tokens.
// ---------------------------------------------------------------------------
__global__ __launch_bounds__(512) void k_pre(
    const float* __restrict__ x,
    const float* __restrict__ sb_wq, const float* __restrict__ sb_bq,
    const float* __restrict__ sb_ww, const float* __restrict__ sb_bw,
    const float* __restrict__ p_win, const float* __restrict__ p_bin)
{
    __shared__ float xs[16 * 512];
    const int t0 = blockIdx.x * 16;
    const int tid = threadIdx.x;
    const float* xb = x + (size_t)t0 * 512;
    for (int idx = tid; idx < 16 * 512; idx += 512) xs[idx] = xb[idx];
    __syncthreads();

    const int c = tid;
    const float* W; int ld; float bias;
    if (c < 128)      { W = sb_wq + c;         ld = 128; bias = sb_bq[c]; }
    else if (c < 256) { W = sb_ww + (c - 128); ld = 128; bias = sb_bw[c - 128]; }
    else              { W = p_win + (c - 256); ld = 256; bias = p_bin[c - 256]; }

    float acc[16];
#pragma unroll
    for (int t = 0; t < 16; t++) acc[t] = 0.f;
    for (int i = 0; i < 512; i++) {
        float w = W[(size_t)i * ld];
#pragma unroll
        for (int t = 0; t < 16; t++) acc[t] += xs[t * 512 + i] * w;
    }
#pragma unroll
    for (int t = 0; t < 16; t++)
        g_qwx[((size_t)(t0 + t)) * 512 + c] = acc[t] + bias;
}

// ---------------------------------------------------------------------------
// Kernel 1b: precompute ba softmax
// ---------------------------------------------------------------------------
__global__ __launch_bounds__(256) void k_ba(
    const float* __restrict__ b_wq, const float* __restrict__ b_bq,
    const float* __restrict__ b_keys)
{
    __shared__ float s_x[8 * 256];
    __shared__ float s_keys[64 * 129];
    __shared__ float s_bq[8 * 128];
    const int t0 = blockIdx.x * 8;
    const int tid = threadIdx.x;

    for (int idx = tid; idx < 8 * 256; idx += 256) {
        int t = idx >> 8, i = idx & 255;
        s_x[idx] = g_qwx[((size_t)(t0 + t)) * 512 + 256 + i];
    }
    for (int idx = tid; idx < 64 * 128; idx += 256) {
        int n = idx >> 7, k = idx & 127;
        s_keys[n * 129 + k] = b_keys[idx];
    }
    __syncthreads();

    {
        int c = tid & 127, tg = tid >> 7;
        float acc[4];
        float bb = b_bq[c];
#pragma unroll
        for (int t = 0; t < 4; t++) acc[t] = bb;
        for (int i = 0; i < 256; i++) {
            float w = b_wq[i * 128 + c];
#pragma unroll
            for (int t = 0; t < 4; t++) acc[t] += s_x[(tg * 4 + t) * 256 + i] * w;
        }
#pragma unroll
        for (int t = 0; t < 4; t++) s_bq[(tg * 4 + t) * 128 + c] = acc[t];
    }
    __syncthreads();

    {
        const float invscale = 0.08838834764831845f;
        int t = tid >> 5, lane = tid & 31;
        float l0 = 0.f, l1 = 0.f;
        for (int k = 0; k < 128; k++) {
            float q = s_bq[t * 128 + k];
            l0 += q * s_keys[lane * 129 + k];
            l1 += q * s_keys[(lane + 32) * 129 + k];
        }
        l0 *= invscale; l1 *= invscale;
        float m = fmaxf(l0, l1);
#pragma unroll
        for (int o = 16; o > 0; o >>= 1) m = fmaxf(m, __shfl_xor_sync(0xffffffffu, m, o));
        float e0 = expf(l0 - m), e1 = expf(l1 - m);
        float ssum = e0 + e1;
#pragma unroll
        for (int o = 16; o > 0; o >>= 1) ssum += __shfl_xor_sync(0xffffffffu, ssum, o);
        float inv = 1.f / ssum;
        float* dst = g_ba + ((size_t)(t0 + t)) * 64;
        dst[lane] = e0 * inv;
        dst[lane + 32] = e1 * inv;
    }
}

// ---------------------------------------------------------------------------
// Kernel 2: recurrent core. 32 CTAs = 8 batches x cluster of 4.
// Column-split GEMVs, DSMEM exchange; small ops replicated per CTA.
// ---------------------------------------------------------------------------
__global__ __launch_bounds__(512, 1) __cluster_dims__(4, 1, 1)
void k_rec(
    const float* __restrict__ sb_init, const float* __restrict__ bp_b,
    const float* __restrict__ dn_bqkv, const float* __restrict__ dn_bbeta,
    const float* __restrict__ dn_bo, const float* __restrict__ dn_lng,
    const float* __restrict__ dn_lnb, const float* __restrict__ sup_b)
{
    extern __shared__ float sm[];
    float* s_slots = sm;               // 8192
    float* s_part  = sm + 8192;        // 4096
    float* s_bqkv  = sm + 12288;       // 1536
    float* s_bo    = sm + 13824;       // 512
    float* s_lng   = sm + 14336;       // 512
    float* s_lnb   = sm + 14848;       // 512
    float* s_bpb   = sm + 15360;       // 256
    float* s_supb  = sm + 15616;       // 128
    float* s_bbeta = sm + 15744;       // 8
    float* s_q     = sm + 15752;       // 128
    float* s_wr    = sm + 15880;       // 128
    float* s_xh    = sm + 16008;       // 256
    float* s_abuf  = sm + 16264;       // 64
    float* s_a     = sm + 16328;       // 64
    float* s_g     = sm + 16392;       // 64
    float* s_ba    = sm + 16456;       // 64
    float* s_g2    = sm + 16520;       // 64
    float* s_bind  = sm + 16584;       // 128
    float* s_qkv   = sm + 16712;       // 768
    float* s_khn   = sm + 17480;       // 256
    float* s_beta  = sm + 17736;       // 4
    float* s_inv   = sm + 17740;       // 4
    float* s_o     = sm + 17744;       // 256
    float* s_resid = sm + 18000;       // 256
    float* s_u     = sm + 18256;       // 128
    float* s_exch  = sm + 18384;       // 256
    float* s_wout  = sm + 18640;       // 256
    float* s_mv    = sm + 18896;       // 2

    const int tid = threadIdx.x;
    const int b  = blockIdx.x >> 2;
    const int rk = blockIdx.x & 3;
    const float invscale = 0.08838834764831845f;

    for (int idx = tid; idx < Nv * SDv; idx += 512) s_slots[idx] = sb_init[idx];
    for (int i = tid; i < 1536; i += 512) s_bqkv[i] = dn_bqkv[i];
    if (tid < 512) { s_bo[tid] = dn_bo[tid]; s_lng[tid] = dn_lng[tid]; s_lnb[tid] = dn_lnb[tid]; }
    if (tid < 256) s_bpb[tid] = bp_b[tid];
    if (tid < 128) s_supb[tid] = sup_b[tid];
    if (tid < 8) s_bbeta[tid] = dn_bbeta[tid];

    float Sreg[64];
#pragma unroll
    for (int j = 0; j < 64; j++) Sreg[j] = 0.f;
    const int l_own = tid >> 8;
    const int h_own = (tid >> 6) & 3;
    const int i_own = tid & 63;
    const int wp = tid >> 5, la = tid & 31;
    __syncthreads();
    cluster_sync_();

    for (int s = 0; s < Sv; ++s) {
        const size_t tok = (size_t)(b * Sv + s);
        const float* qwx = g_qwx + tok * 512;
        if (tid < 128) s_q[tid] = qwx[tid];
        else if (tid < 256) s_wr[tid - 128] = qwx[tid];
        else s_xh[tid - 256] = qwx[tid];
        if (tid < 64) {
            float v = g_ba[tok * 64 + tid];
            s_ba[tid] = v;
            s_g2[tid] = 1.f / (1.f + expf(-v));
        }
        __syncthreads();

        // --- attn1 logits ---
#pragma unroll
        for (int r = 0; r < 4; r++) {
            int n = wp * 4 + r;
            const float* row = s_slots + n * 128;
            float p = row[la] * s_q[la] + row[la + 32] * s_q[la + 32]
                    + row[la + 64] * s_q[la + 64] + row[la + 96] * s_q[la + 96];
#pragma unroll
            for (int o = 16; o > 0; o >>= 1) p += __shfl_xor_sync(0xffffffffu, p, o);
            if (la == 0) s_abuf[n] = p * invscale;
        }
        __syncthreads();
        // --- softmax + gate (warp 0) ---
        if (tid < 32) {
            float l0 = s_abuf[tid], l1 = s_abuf[tid + 32];
            float m = fmaxf(l0, l1);
#pragma unroll
            for (int o = 16; o > 0; o >>= 1) m = fmaxf(m, __shfl_xor_sync(0xffffffffu, m, o));
            float e0 = expf(l0 - m), e1 = expf(l1 - m);
            float ss = e0 + e1;
#pragma unroll
            for (int o = 16; o > 0; o >>= 1) ss += __shfl_xor_sync(0xffffffffu, ss, o);
            float inv = 1.f / ss;
            float a0 = e0 * inv, a1 = e1 * inv;
            s_a[tid] = a0; s_a[tid + 32] = a1;
            s_g[tid] = 1.f / (1.f + expf(-a0));
            s_g[tid + 32] = 1.f / (1.f + expf(-a1));
        }
        __syncthreads();

        // --- read = a @ slots (export only, rank 0), then slot update #1 ---
        {
            int d = tid & 127, ch = tid >> 7;
            float p = 0.f;
#pragma unroll
            for (int k = 0; k < 16; k++) { int n = ch * 16 + k; p += s_a[n] * s_slots[n * 128 + d]; }
            s_part[ch * 128 + d] = p;
        }
        __syncthreads();
        if (tid < 128 && rk == 0) {
            float rv = s_part[tid] + s_part[128 + tid] + s_part[256 + tid] + s_part[384 + tid];
            g_rx[tok * 384 + tid] = rv;
        }
        for (int idx = tid; idx < Nv * SDv; idx += 512) {
            int n = idx >> 7, d = idx & 127;
            float g = s_g[n];
            s_slots[idx] = (1.f - g) * s_slots[idx] + g * (s_a[n] * s_wr[d]);
        }
        __syncthreads();

        // --- bindings = ba @ slots (updated) ---
        {
            int d = tid & 127, ch = tid >> 7;
            float p = 0.f;
#pragma unroll
            for (int k = 0; k < 16; k++) { int n = ch * 16 + k; p += s_ba[n] * s_slots[n * 128 + d]; }
            s_part[ch * 128 + d] = p;
        }
        __syncthreads();
        if (tid < 128)
            s_bind[tid] = s_part[tid] + s_part[128 + tid] + s_part[256 + tid] + s_part[384 + tid];
        __syncthreads();

        // --- bp: 64 cols per rank ---
        if (tid < 256) {
            int cgp = tid & 7, iseg = tid >> 3;           // rows/iseg = 4
            const uint4* W = ((const uint4*)(g_h + H_BPW)) + (size_t)(iseg * 4) * 32 + (rk * 8 + cgp);
            float a0=0,a1=0,a2=0,a3=0,a4=0,a5=0,a6=0,a7=0;
#pragma unroll
            for (int r = 0; r < 4; r++) {
                float xv = s_bind[iseg * 4 + r];
                uint4 w = W[(size_t)r * 32];
                half2 h0 = *(half2*)&w.x, h1 = *(half2*)&w.y, h2 = *(half2*)&w.z, h3 = *(half2*)&w.w;
                a0 += xv * __low2float(h0); a1 += xv * __high2float(h0);
                a2 += xv * __low2float(h1); a3 += xv * __high2float(h1);
                a4 += xv * __low2float(h2); a5 += xv * __high2float(h2);
                a6 += xv * __low2float(h3); a7 += xv * __high2float(h3);
            }
            float* P = s_part + iseg * 64 + cgp * 8;
            P[0]=a0; P[1]=a1; P[2]=a2; P[3]=a3; P[4]=a4; P[5]=a5; P[6]=a6; P[7]=a7;
        }
        __syncthreads();
        if (tid < 64) {
            int c = rk * 64 + tid;
            float p = s_bpb[c];
            for (int sg = 0; sg < 32; sg++) p += s_part[sg * 64 + tid];
#pragma unroll
            for (int rr = 0; rr < 4; rr++) st_cluster_f32(s_exch + c, rr, p);
        }
        cluster_sync_();
        if (tid < 256) s_xh[tid] += s_exch[tid];
        __syncthreads();

        // --- DeltaNet layers ---
#pragma unroll
        for (int l = 0; l < 2; l++) {
            // qkv: 192 cols per rank (threads 0-383) + beta replicated (warps 12-15)
            if (tid < 384) {
                int cgp = tid % 24, iseg = tid / 24;      // rows/iseg = 16
                const uint4* W = ((const uint4*)(g_h + H_QKV)) + (size_t)l * 24576
                               + (size_t)(iseg * 16) * 96 + (rk * 24 + cgp);
                float a0=0,a1=0,a2=0,a3=0,a4=0,a5=0,a6=0,a7=0;
#pragma unroll
                for (int r = 0; r < 16; r++) {
                    float xv = s_xh[iseg * 16 + r];
                    uint4 w = W[(size_t)r * 96];
                    half2 h0 = *(half2*)&w.x, h1 = *(half2*)&w.y, h2 = *(half2*)&w.z, h3 = *(half2*)&w.w;
                    a0 += xv * __low2float(h0); a1 += xv * __high2float(h0);
                    a2 += xv * __low2float(h1); a3 += xv * __high2float(h1);
                    a4 += xv * __low2float(h2); a5 += xv * __high2float(h2);
                    a6 += xv * __low2float(h3); a7 += xv * __high2float(h3);
                }
                float* P = s_part + iseg * 192 + cgp * 8;
                P[0]=a0; P[1]=a1; P[2]=a2; P[3]=a3; P[4]=a4; P[5]=a5; P[6]=a6; P[7]=a7;
            } else {
                int c = (tid >> 5) - 12;
                float acc = 0.f;
                const __half* Wb = g_h + H_WBETA + (size_t)l * 1024;
#pragma unroll
                for (int k = 0; k < 8; k++) {
                    int i = k * 32 + la;
                    acc += s_xh[i] * __half2float(Wb[i * 4 + c]);
                }
#pragma unroll
                for (int o = 16; o > 0; o >>= 1) acc += __shfl_xor_sync(0xffffffffu, acc, o);
                if (la == 0) {
                    float z = acc + s_bbeta[l * 4 + c];
                    s_beta[c] = 1.f / (1.f + expf(-z));
                }
            }
            __syncthreads();
            if (tid < 192) {
                int c = rk * 192 + tid;
                float p = s_bqkv[l * 768 + c];
                for (int sg = 0; sg < 16; sg++) p += s_part[sg * 192 + tid];
#pragma unroll
                for (int rr = 0; rr < 4; rr++) st_cluster_f32(s_qkv + c, rr, p);
            }
            cluster_sync_();

            // k-norm (warp per head, threads 0-127)
            if (tid < 128) {
                int h = tid >> 5, l2 = tid & 31;
                float k0 = s_qkv[256 + h * 64 + l2], k1 = s_qkv[256 + h * 64 + 32 + l2];
                float ss = k0 * k0 + k1 * k1;
#pragma unroll
                for (int o = 16; o > 0; o >>= 1) ss += __shfl_xor_sync(0xffffffffu, ss, o);
                if (l2 == 0) s_inv[h] = 1.f / (sqrtf(ss) + 1e-6f);
            }
            __syncthreads();
            if (tid < 256) s_khn[tid] = s_qkv[256 + tid] * s_inv[tid >> 6];
            __syncthreads();
            // state update (replicated; owners of this layer act)
            if (l_own == l) {
                const float* kh = s_khn + h_own * 64;
                const float* qh = s_qkv + h_own * 64;
                float sk = 0.f;
#pragma unroll
                for (int j = 0; j < 64; j++) sk += Sreg[j] * kh[j];
                float delta = s_beta[h_own] * (s_qkv[512 + h_own * 64 + i_own] - sk);
                float oacc = 0.f;
#pragma unroll
                for (int j = 0; j < 64; j++) { Sreg[j] += delta * kh[j]; oacc += Sreg[j] * qh[j]; }
                s_o[h_own * 64 + i_own] = oacc;
            }
            __syncthreads();
            // wo: 64 cols per rank
            if (tid < 256) {
                int cgp = tid & 7, iseg = tid >> 3;       // rows/iseg = 8
                const uint4* W = ((const uint4*)(g_h + H_WO)) + (size_t)l * 8192
                               + (size_t)(iseg * 8) * 32 + (rk * 8 + cgp);
                float a0=0,a1=0,a2=0,a3=0,a4=0,a5=0,a6=0,a7=0;
#pragma unroll
                for (int r = 0; r < 8; r++) {
                    float xv = s_o[iseg * 8 + r];
                    uint4 w = W[(size_t)r * 32];
                    half2 h0 = *(half2*)&w.x, h1 = *(half2*)&w.y, h2 = *(half2*)&w.z, h3 = *(half2*)&w.w;
                    a0 += xv * __low2float(h0); a1 += xv * __high2float(h0);
                    a2 += xv * __low2float(h1); a3 += xv * __high2float(h1);
                    a4 += xv * __low2float(h2); a5 += xv * __high2float(h2);
                    a6 += xv * __low2float(h3); a7 += xv * __high2float(h3);
                }
                float* P = s_part + iseg * 64 + cgp * 8;
                P[0]=a0; P[1]=a1; P[2]=a2; P[3]=a3; P[4]=a4; P[5]=a5; P[6]=a6; P[7]=a7;
            }
            __syncthreads();
            if (tid < 64) {
                int c = rk * 64 + tid;
                float p = s_bo[l * 256 + c];
                for (int sg = 0; sg < 32; sg++) p += s_part[sg * 64 + tid];
#pragma unroll
                for (int rr = 0; rr < 4; rr++) st_cluster_f32(s_wout + c, rr, p);
            }
            cluster_sync_();
            if (tid < 256) s_resid[tid] = s_xh[tid] + s_wout[tid];
            __syncthreads();
            // LN (warp 0)
            if (tid < 32) {
                float s1 = 0.f, s2 = 0.f;
#pragma unroll
                for (int k = 0; k < 8; k++) { float v = s_resid[tid * 8 + k]; s1 += v; s2 += v * v; }
#pragma unroll
                for (int o = 16; o > 0; o >>= 1) {
                    s1 += __shfl_xor_sync(0xffffffffu, s1, o);
                    s2 += __shfl_xor_sync(0xffffffffu, s2, o);
                }
                if (tid == 0) {
                    float m = s1 / 256.f;
                    float var = s2 / 256.f - m * m;
                    s_mv[0] = m; s_mv[1] = rsqrtf(var + 1e-5f);
                }
            }
            __syncthreads();
            if (tid < 256)
                s_xh[tid] = (s_resid[tid] - s_mv[0]) * s_mv[1] * s_lng[l * 256 + tid] + s_lnb[l * 256 + tid];
            __syncthreads();
        }

        // --- sup: 32 cols per rank; export xh (rank 0) ---
        if (tid < 256) {
            int cgp = tid & 3, iseg = tid >> 2;           // rows/iseg = 4
            const uint4* W = ((const uint4*)(g_h + H_SUPW)) + (size_t)(iseg * 4) * 16 + (rk * 4 + cgp);
            float a0=0,a1=0,a2=0,a3=0,a4=0,a5=0,a6=0,a7=0;
#pragma unroll
            for (int r = 0; r < 4; r++) {
                float xv = s_xh[iseg * 4 + r];
                uint4 w = W[(size_t)r * 16];
                half2 h0 = *(half2*)&w.x, h1 = *(half2*)&w.y, h2 = *(half2*)&w.z, h3 = *(half2*)&w.w;
                a0 += xv * __low2float(h0); a1 += xv * __high2float(h0);
                a2 += xv * __low2float(h1); a3 += xv * __high2float(h1);
                a4 += xv * __low2float(h2); a5 += xv * __high2float(h2);
                a6 += xv * __low2float(h3); a7 += xv * __high2float(h3);
            }
            float* P = s_part + iseg * 32 + cgp * 8;
            P[0]=a0; P[1]=a1; P[2]=a2; P[3]=a3; P[4]=a4; P[5]=a5; P[6]=a6; P[7]=a7;
        } else if (rk == 0) {
            g_rx[tok * 384 + 128 + (tid - 256)] = s_xh[tid - 256];
        }
        __syncthreads();
        if (tid < 32) {
            int c = rk * 32 + tid;
            float p = 0.f;
            for (int sg = 0; sg < 64; sg++) p += s_part[sg * 32 + tid];
#pragma unroll
            for (int rr = 0; rr < 4; rr++) st_cluster_f32(s_u + c, rr, p);
        }
        cluster_sync_();
        // slot update #2 (replicated)
        for (int idx = tid; idx < Nv * SDv; idx += 512) {
            int n = idx >> 7, d = idx & 127;
            float g = s_g2[n];
            s_slots[idx] = (1.f - g) * s_slots[idx] + g * (s_ba[n] * s_u[d] + s_supb[d]);
        }
        __syncthreads();
    }
}

// ---------------------------------------------------------------------------
// Kernel 3: ypre = read@sb_wo + xh@op_w + biases; out = LN(ypre) @ ow + ob.
// ---------------------------------------------------------------------------
__global__ __launch_bounds__(512) void k_out(
    const float* __restrict__ sb_wo, const float* __restrict__ sb_bo,
    const float* __restrict__ op_w, const float* __restrict__ op_b,
    const float* __restrict__ oln_g, const float* __restrict__ oln_b,
    const float* __restrict__ ow, const float* __restrict__ ob,
    float* __restrict__ out)
{
    __shared__ float rx[8 * 384];
    __shared__ float yt[8 * 512];
    __shared__ float mv[8][2];
    const int t0 = blockIdx.x * 8;
    const int tid = threadIdx.x;
    const float* src = g_rx + (size_t)t0 * 384;
    for (int idx = tid; idx < 8 * 384; idx += 512) rx[idx] = src[idx];
    __syncthreads();

    {
        float acc[8];
        float bias = sb_bo[tid] + op_b[tid];
#pragma unroll
        for (int t = 0; t < 8; t++) acc[t] = bias;
        const float* w1 = sb_wo + tid;
        for (int i = 0; i < 128; i++) {
            float wv = w1[(size_t)i * 512];
#pragma unroll
            for (int t = 0; t < 8; t++) acc[t] += rx[t * 384 + i] * wv;
        }
        const float* w2 = op_w + tid;
        for (int i = 0; i < 256; i++) {
            float wv = w2[(size_t)i * 512];
#pragma unroll
            for (int t = 0; t < 8; t++) acc[t] += rx[t * 384 + 128 + i] * wv;
        }
#pragma unroll
        for (int t = 0; t < 8; t++) yt[t * 512 + tid] = acc[t];
    }
    __syncthreads();

    if (tid < 256) {
        int tt = tid >> 5, lane = tid & 31;
        float s1 = 0.f, s2 = 0.f;
        for (int i = lane; i < 512; i += 32) { float v = yt[tt * 512 + i]; s1 += v; s2 += v * v; }
#pragma unroll
        for (int o = 16; o > 0; o >>= 1) {
            s1 += __shfl_xor_sync(0xffffffffu, s1, o);
            s2 += __shfl_xor_sync(0xffffffffu, s2, o);
        }
        if (lane == 0) {
            float m = s1 / 512.f;
            mv[tt][0] = m;
            mv[tt][1] = rsqrtf(s2 / 512.f - m * m + 1e-5f);
        }
    }
    __syncthreads();
    for (int idx = tid; idx < 8 * 512; idx += 512) {
        int tt = idx >> 9, c = idx & 511;
        yt[idx] = (yt[idx] - mv[tt][0]) * mv[tt][1] * oln_g[c] + oln_b[c];
    }
    __syncthreads();

    float acc[8];
#pragma unroll
    for (int t = 0; t < 8; t++) acc[t] = ob[tid];
    const float* w = ow + tid;
    for (int i = 0; i < 512; i++) {
        float wv = w[(size_t)i * 512];
#pragma unroll
        for (int t = 0; t < 8; t++) acc[t] += yt[t * 512 + i] * wv;
    }
    float* dst = out + (size_t)t0 * 512;
#pragma unroll
    for (int t = 0; t < 8; t++) dst[t * 512 + tid] = acc[t];
}

// ---------------------------------------------------------------------------
extern "C" void kernel_launch(void* const* d_in, const int* in_sizes, int n_in,
                              void* d_out, int out_size)
{
    const float* x        = (const float*)d_in[0];
    const float* sb_init  = (const float*)d_in[1];
    const float* sb_wq    = (const float*)d_in[2];
    const float* sb_bq    = (const float*)d_in[3];
    const float* sb_ww    = (const float*)d_in[4];
    const float* sb_bw    = (const float*)d_in[5];
    const float* sb_wo    = (const float*)d_in[6];
    const float* sb_bo    = (const float*)d_in[7];
    const float* p_win    = (const float*)d_in[8];
    const float* p_bin    = (const float*)d_in[9];
    const float* b_wq     = (const float*)d_in[10];
    const float* b_bq     = (const float*)d_in[11];
    const float* b_keys   = (const float*)d_in[12];
    const float* bp_w     = (const float*)d_in[13];
    const float* bp_b     = (const float*)d_in[14];
    const float* dn_wqkv  = (const float*)d_in[15];
    const float* dn_bqkv  = (const float*)d_in[16];
    const float* dn_wbeta = (const float*)d_in[17];
    const float* dn_bbeta = (const float*)d_in[18];
    const float* dn_wo    = (const float*)d_in[19];
    const float* dn_bo    = (const float*)d_in[20];
    const float* dn_lng   = (const float*)d_in[21];
    const float* dn_lnb   = (const float*)d_in[22];
    const float* sup_w    = (const float*)d_in[23];
    const float* sup_b    = (const float*)d_in[24];
    const float* op_w     = (const float*)d_in[25];
    const float* op_b     = (const float*)d_in[26];
    const float* oln_g    = (const float*)d_in[27];
    const float* oln_b    = (const float*)d_in[28];
    const float* ow       = (const float*)d_in[29];
    const float* ob       = (const float*)d_in[30];

    static bool attr_set = false;
    if (!attr_set) {
        cudaFuncSetAttribute(k_rec, cudaFuncAttributeMaxDynamicSharedMemorySize, 76 * 1024);
        attr_set = true;
    }

    k_cvt<<<(H_TOTAL + 511) / 512, 512>>>(dn_wqkv, dn_wo, bp_w, sup_w, dn_wbeta);
    k_pre<<<512, 512>>>(x, sb_wq, sb_bq, sb_ww, sb_bw, p_win, p_bin);
    k_ba<<<1024, 256>>>(b_wq, b_bq, b_keys);
    k_rec<<<32, 512, 76 * 1024>>>(sb_init, bp_b, dn_bqkv, dn_bbeta, dn_bo,
                                  dn_lng, dn_lnb, sup_b);
    k_out<<<1024, 512>>>(sb_wo, sb_bo, op_w, op_b, oln_g, oln_b, ow, ob, (float*)d_out);
}

// round 6
// speedup vs baseline: 3.4786x; 1.0826x over previous
#include <cuda_runtime.h>
#include <cuda_fp16.h>
#include <cstdint>
#include <math.h>

#define Bv 8
#define Sv 1024
#define Dv 512
#define Hv 256
#define Nv 64
#define SDv 128
#define NHv 4
#define DHv 64

#define CLW 8   // cluster width (ranks per batch)

// ---- device scratch (no allocations allowed) ----
__device__ float g_qwx[(size_t)Bv * Sv * 512];   // per token: [q(128) | wr(128) | xh0(256)]
__device__ float g_ba[(size_t)Bv * Sv * 64];     // precomputed attn2 softmax
__device__ float g_rx[(size_t)Bv * Sv * 384];    // per token: [read(128) | xh_final(256)]
__device__ __align__(256) __half g_h[591872];    // fp16 weight pack

#define H_QKV   0          // 2*256*768 = 393216
#define H_WO    393216     // 2*256*256 = 131072
#define H_BPW   524288     // 128*256   = 32768
#define H_SUPW  557056     // 256*128   = 32768
#define H_WBETA 589824     // 2*256*4   = 2048
#define H_TOTAL 591872

// smem float-index layout for k_rec
#define SM_SLOTS 0        // 8192
#define SM_PART  8192     // 3072
#define SM_Q     11264
#define SM_WR    11392
#define SM_XH    11520
#define SM_ABUF  11776
#define SM_A     11840
#define SM_G     11904
#define SM_BA    11968
#define SM_G2    12032
#define SM_CB    12096
#define SM_C1    12160
#define SM_C2    12224
#define SM_T1    12288
#define SM_BIND  12352
#define SM_QKV   12480
#define SM_KHN   13248
#define SM_BETA  13504
#define SM_O     13508
#define SM_RESID 13764
#define SM_U     14020
#define SM_EXCH  14148
#define SM_WOUT  14404
#define SM_MV    14660
#define SM_BQKV2 14664    // 192 (rank slice)
#define SM_BO2   14856    // 64
#define SM_LNG   14920    // 512
#define SM_LNB   15432    // 512
#define SM_BPB2  15944    // 32
#define SM_SUPB  15976    // 128
#define SM_BBETA 16104    // 8
#define SM_HBASE 16128    // halves start here (byte 64512, 16B aligned)
// half offsets (relative to half base)
#define WS_QKV  0         // 2*256*96 = 49152
#define WS_WO   49152     // 2*256*32 = 16384
#define WS_BP   65536     // 128*32   = 4096
#define WS_SUP  69632     // 256*16   = 4096
#define WS_BETA 73728     // 2*256*4  = 2048
#define SMEM_REC_BYTES (SM_HBASE * 4 + 75776 * 2)   // 216064

// ---- cluster helpers ----
__device__ __forceinline__ void cluster_sync_() {
    asm volatile("barrier.cluster.arrive.aligned;" ::: "memory");
    asm volatile("barrier.cluster.wait.aligned;" ::: "memory");
}
__device__ __forceinline__ void st_cluster_f32(float* p, int rr, float v) {
    unsigned int l = (unsigned int)__cvta_generic_to_shared(p);
    unsigned int r;
    asm volatile("mapa.shared::cluster.u32 %0, %1, %2;" : "=r"(r) : "r"(l), "r"(rr));
    asm volatile("st.shared::cluster.f32 [%0], %1;" :: "r"(r), "f"(v) : "memory");
}
__device__ __forceinline__ void bcast_all_ranks(float* p, float v) {
#pragma unroll
    for (int rr = 0; rr < CLW; rr++) st_cluster_f32(p, rr, v);
}

// fp16 vec8 FMA helper
#define FMA8(w, xv) do { \
    half2 h0 = *(half2*)&(w).x, h1 = *(half2*)&(w).y, h2 = *(half2*)&(w).z, h3 = *(half2*)&(w).w; \
    a0 += (xv) * __low2float(h0); a1 += (xv) * __high2float(h0); \
    a2 += (xv) * __low2float(h1); a3 += (xv) * __high2float(h1); \
    a4 += (xv) * __low2float(h2); a5 += (xv) * __high2float(h2); \
    a6 += (xv) * __low2float(h3); a7 += (xv) * __high2float(h3); } while (0)

// ---------------------------------------------------------------------------
// Convert recurrent weights to fp16 pack
// ---------------------------------------------------------------------------
__global__ __launch_bounds__(512) void k_cvt(
    const float* __restrict__ wqkv, const float* __restrict__ wo,
    const float* __restrict__ bpw, const float* __restrict__ supw,
    const float* __restrict__ wbeta)
{
    int i = blockIdx.x * 512 + threadIdx.x;
    if (i >= H_TOTAL) return;
    float v;
    if (i < H_WO)        v = wqkv[i];
    else if (i < H_BPW)  v = wo[i - H_WO];
    else if (i < H_SUPW) v = bpw[i - H_BPW];
    else if (i < H_WBETA) v = supw[i - H_SUPW];
    else                 v = wbeta[i - H_WBETA];
    g_h[i] = __float2half(v);
}

// ---------------------------------------------------------------------------
// Kernel 1: q/wr/xh0 for all tokens.
// ---------------------------------------------------------------------------
__global__ __launch_bounds__(512) void k_pre(
    const float* __restrict__ x,
    const float* __restrict__ sb_wq, const float* __restrict__ sb_bq,
    const float* __restrict__ sb_ww, const float* __restrict__ sb_bw,
    const float* __restrict__ p_win, const float* __restrict__ p_bin)
{
    __shared__ float xs[16 * 512];
    const int t0 = blockIdx.x * 16;
    const int tid = threadIdx.x;
    const float* xb = x + (size_t)t0 * 512;
    for (int idx = tid; idx < 16 * 512; idx += 512) xs[idx] = xb[idx];
    __syncthreads();

    const int c = tid;
    const float* W; int ld; float bias;
    if (c < 128)      { W = sb_wq + c;         ld = 128; bias = sb_bq[c]; }
    else if (c < 256) { W = sb_ww + (c - 128); ld = 128; bias = sb_bw[c - 128]; }
    else              { W = p_win + (c - 256); ld = 256; bias = p_bin[c - 256]; }

    float acc[16];
#pragma unroll
    for (int t = 0; t < 16; t++) acc[t] = 0.f;
    for (int i = 0; i < 512; i++) {
        float w = W[(size_t)i * ld];
#pragma unroll
        for (int t = 0; t < 16; t++) acc[t] += xs[t * 512 + i] * w;
    }
#pragma unroll
    for (int t = 0; t < 16; t++)
        g_qwx[((size_t)(t0 + t)) * 512 + c] = acc[t] + bias;
}

// ---------------------------------------------------------------------------
// Kernel 1b: precompute ba softmax
// ---------------------------------------------------------------------------
__global__ __launch_bounds__(256) void k_ba(
    const float* __restrict__ b_wq, const float* __restrict__ b_bq,
    const float* __restrict__ b_keys)
{
    __shared__ float s_x[8 * 256];
    __shared__ float s_keys[64 * 129];
    __shared__ float s_bq[8 * 128];
    const int t0 = blockIdx.x * 8;
    const int tid = threadIdx.x;

    for (int idx = tid; idx < 8 * 256; idx += 256) {
        int t = idx >> 8, i = idx & 255;
        s_x[idx] = g_qwx[((size_t)(t0 + t)) * 512 + 256 + i];
    }
    for (int idx = tid; idx < 64 * 128; idx += 256) {
        int n = idx >> 7, k = idx & 127;
        s_keys[n * 129 + k] = b_keys[idx];
    }
    __syncthreads();

    {
        int c = tid & 127, tg = tid >> 7;
        float acc[4];
        float bb = b_bq[c];
#pragma unroll
        for (int t = 0; t < 4; t++) acc[t] = bb;
        for (int i = 0; i < 256; i++) {
            float w = b_wq[i * 128 + c];
#pragma unroll
            for (int t = 0; t < 4; t++) acc[t] += s_x[(tg * 4 + t) * 256 + i] * w;
        }
#pragma unroll
        for (int t = 0; t < 4; t++) s_bq[(tg * 4 + t) * 128 + c] = acc[t];
    }
    __syncthreads();

    {
        const float invscale = 0.08838834764831845f;
        int t = tid >> 5, lane = tid & 31;
        float l0 = 0.f, l1 = 0.f;
        for (int k = 0; k < 128; k++) {
            float q = s_bq[t * 128 + k];
            l0 += q * s_keys[lane * 129 + k];
            l1 += q * s_keys[(lane + 32) * 129 + k];
        }
        l0 *= invscale; l1 *= invscale;
        float m = fmaxf(l0, l1);
#pragma unroll
        for (int o = 16; o > 0; o >>= 1) m = fmaxf(m, __shfl_xor_sync(0xffffffffu, m, o));
        float e0 = expf(l0 - m), e1 = expf(l1 - m);
        float ssum = e0 + e1;
#pragma unroll
        for (int o = 16; o > 0; o >>= 1) ssum += __shfl_xor_sync(0xffffffffu, ssum, o);
        float inv = 1.f / ssum;
        float* dst = g_ba + ((size_t)(t0 + t)) * 64;
        dst[lane] = e0 * inv;
        dst[lane + 32] = e1 * inv;
    }
}

// ---------------------------------------------------------------------------
// Kernel 2: recurrent core. 64 CTAs = 8 batches x cluster of 8.
// Per-rank weight slices resident in SMEM; DSMEM exchange for GEMV outputs.
// ---------------------------------------------------------------------------
__global__ __launch_bounds__(512, 1) __cluster_dims__(CLW, 1, 1)
void k_rec(
    const float* __restrict__ sb_init, const float* __restrict__ bp_b,
    const float* __restrict__ dn_bqkv, const float* __restrict__ dn_bbeta,
    const float* __restrict__ dn_bo, const float* __restrict__ dn_lng,
    const float* __restrict__ dn_lnb, const float* __restrict__ sup_b)
{
    extern __shared__ float sm[];
    __half* hs = (__half*)(sm + SM_HBASE);

    const int tid = threadIdx.x;
    const int b  = blockIdx.x / CLW;
    const int rk = blockIdx.x % CLW;
    const float invscale = 0.08838834764831845f;

    // ---- one-time: slots, biases, weight slices into smem ----
    for (int idx = tid; idx < Nv * SDv; idx += 512) sm[SM_SLOTS + idx] = sb_init[idx];
    if (tid < 192) sm[SM_BQKV2 + tid] = dn_bqkv[(tid / 96) * 768 + rk * 96 + (tid % 96)];
    if (tid < 64)  sm[SM_BO2 + tid]   = dn_bo[(tid / 32) * 256 + rk * 32 + (tid % 32)];
    if (tid < 512) { sm[SM_LNG + tid] = dn_lng[tid]; sm[SM_LNB + tid] = dn_lnb[tid]; }
    if (tid < 32)  sm[SM_BPB2 + tid]  = bp_b[rk * 32 + tid];
    if (tid < 128) sm[SM_SUPB + tid]  = sup_b[tid];
    if (tid < 8)   sm[SM_BBETA + tid] = dn_bbeta[tid];

    {   // qkv slice: 6144 uint4
        const uint4* src = (const uint4*)(g_h + H_QKV);
        uint4* dst = (uint4*)(hs + WS_QKV);
        for (int i = tid; i < 6144; i += 512) {
            int rowL = i / 12, c = i % 12;
            dst[rowL * 12 + c] = src[(size_t)rowL * 96 + rk * 12 + c];
        }
    }
    {   // wo slice: 2048 uint4
        const uint4* src = (const uint4*)(g_h + H_WO);
        uint4* dst = (uint4*)(hs + WS_WO);
        for (int i = tid; i < 2048; i += 512) {
            int rowL = i / 4, c = i % 4;
            dst[rowL * 4 + c] = src[(size_t)rowL * 32 + rk * 4 + c];
        }
    }
    {   // bp slice: 512 uint4
        const uint4* src = (const uint4*)(g_h + H_BPW);
        uint4* dst = (uint4*)(hs + WS_BP);
        for (int i = tid; i < 512; i += 512) {
            int row = i / 4, c = i % 4;
            dst[row * 4 + c] = src[(size_t)row * 32 + rk * 4 + c];
        }
    }
    {   // sup slice: 512 uint4
        const uint4* src = (const uint4*)(g_h + H_SUPW);
        uint4* dst = (uint4*)(hs + WS_SUP);
        for (int i = tid; i < 512; i += 512) {
            int row = i / 2, c = i % 2;
            dst[row * 2 + c] = src[(size_t)row * 16 + rk * 2 + c];
        }
    }
    {   // wbeta: replicated, 256 uint4
        const uint4* src = (const uint4*)(g_h + H_WBETA);
        uint4* dst = (uint4*)(hs + WS_BETA);
        for (int i = tid; i < 256; i += 512) dst[i] = src[i];
    }

    // register-resident DeltaNet state (replicated per CTA)
    float Sreg[64];
#pragma unroll
    for (int j = 0; j < 64; j++) Sreg[j] = 0.f;
    const int l_own = tid >> 8;
    const int h_own = (tid >> 6) & 3;
    const int i_own = tid & 63;
    const int wp = tid >> 5, la = tid & 31;
    __syncthreads();
    cluster_sync_();

    for (int s = 0; s < Sv; ++s) {
        const size_t tok = (size_t)(b * Sv + s);
        // --- A: token load ---
        const float* qwx = g_qwx + tok * 512;
        if (tid < 128) sm[SM_Q + tid] = qwx[tid];
        else if (tid < 256) sm[SM_WR + tid - 128] = qwx[tid];
        else sm[SM_XH + tid - 256] = qwx[tid];
        if (tid < 64) {
            float v = g_ba[tok * 64 + tid];
            sm[SM_BA + tid] = v;
            sm[SM_G2 + tid] = 1.f / (1.f + expf(-v));
        }
        __syncthreads();

        // --- B: attn1 logits (warp per 4 slots) ---
#pragma unroll
        for (int r = 0; r < 4; r++) {
            int n = wp * 4 + r;
            const float* row = sm + SM_SLOTS + n * 128;
            float p = row[la] * sm[SM_Q + la] + row[la + 32] * sm[SM_Q + la + 32]
                    + row[la + 64] * sm[SM_Q + la + 64] + row[la + 96] * sm[SM_Q + la + 96];
#pragma unroll
            for (int o = 16; o > 0; o >>= 1) p += __shfl_xor_sync(0xffffffffu, p, o);
            if (la == 0) sm[SM_ABUF + n] = p * invscale;
        }
        __syncthreads();

        // --- C: softmax + all per-n coefficients (warp 0) ---
        if (tid < 32) {
            float l0 = sm[SM_ABUF + tid], l1 = sm[SM_ABUF + tid + 32];
            float m = fmaxf(l0, l1);
#pragma unroll
            for (int o = 16; o > 0; o >>= 1) m = fmaxf(m, __shfl_xor_sync(0xffffffffu, m, o));
            float e0 = expf(l0 - m), e1 = expf(l1 - m);
            float ss = e0 + e1;
#pragma unroll
            for (int o = 16; o > 0; o >>= 1) ss += __shfl_xor_sync(0xffffffffu, ss, o);
            float inv = 1.f / ss;
            float a0 = e0 * inv, a1 = e1 * inv;
            float g0 = 1.f / (1.f + expf(-a0)), g1 = 1.f / (1.f + expf(-a1));
            float ba0 = sm[SM_BA + tid], ba1 = sm[SM_BA + tid + 32];
            float g20 = sm[SM_G2 + tid], g21 = sm[SM_G2 + tid + 32];
            sm[SM_A + tid] = a0;  sm[SM_A + tid + 32] = a1;
            sm[SM_CB + tid] = ba0 * (1.f - g0);       sm[SM_CB + tid + 32] = ba1 * (1.f - g1);
            sm[SM_C1 + tid] = (1.f - g20) * (1.f - g0); sm[SM_C1 + tid + 32] = (1.f - g21) * (1.f - g1);
            sm[SM_C2 + tid] = (1.f - g20) * g0 * a0;  sm[SM_C2 + tid + 32] = (1.f - g21) * g1 * a1;
            sm[SM_T1 + tid] = g20 * ba0;              sm[SM_T1 + tid + 32] = g21 * ba1;
            float cw = ba0 * g0 * a0 + ba1 * g1 * a1;
#pragma unroll
            for (int o = 16; o > 0; o >>= 1) cw += __shfl_xor_sync(0xffffffffu, cw, o);
            if (tid == 0) sm[SM_MV + 2] = cw;
        }
        __syncthreads();

        // --- D: fused read+bind partials over OLD slots ---
        {
            int d = tid & 127, ch = tid >> 7;
            float pr = 0.f, pb = 0.f;
#pragma unroll
            for (int k = 0; k < 16; k++) {
                int n = ch * 16 + k;
                float sv = sm[SM_SLOTS + n * 128 + d];
                pr += sm[SM_A + n] * sv;
                pb += sm[SM_CB + n] * sv;
            }
            sm[SM_PART + ch * 128 + d] = pr;
            sm[SM_PART + 512 + ch * 128 + d] = pb;
        }
        __syncthreads();
        // --- E: reduce: read export + bind ---
        if (tid < 128) {
            float rv = sm[SM_PART + tid] + sm[SM_PART + 128 + tid]
                     + sm[SM_PART + 256 + tid] + sm[SM_PART + 384 + tid];
            if (rk == 0) g_rx[tok * 384 + tid] = rv;
            float bv = sm[SM_PART + 512 + tid] + sm[SM_PART + 640 + tid]
                     + sm[SM_PART + 768 + tid] + sm[SM_PART + 896 + tid]
                     + sm[SM_MV + 2] * sm[SM_WR + tid];
            sm[SM_BIND + tid] = bv;
        }
        __syncthreads();

        // --- F: bp GEMV (tid<128: 4cg x 32iseg, 4 rows each) ---
        if (tid < 128) {
            int cg = tid & 3, iseg = tid >> 2;
            const uint4* W = (const uint4*)(hs + WS_BP) + cg;
            float a0=0,a1=0,a2=0,a3=0,a4=0,a5=0,a6=0,a7=0;
#pragma unroll
            for (int r = 0; r < 4; r++) {
                int row = iseg + 32 * r;
                float xv = sm[SM_BIND + row];
                uint4 w = W[row * 4];
                FMA8(w, xv);
            }
            float* P = sm + SM_PART + iseg * 32 + cg * 8;
            P[0]=a0; P[1]=a1; P[2]=a2; P[3]=a3; P[4]=a4; P[5]=a5; P[6]=a6; P[7]=a7;
        }
        __syncthreads();
        // --- G: reduce + exchange ---
        if (tid < 32) {
            float p = sm[SM_BPB2 + tid];
            for (int sg = 0; sg < 32; sg++) p += sm[SM_PART + sg * 32 + tid];
            bcast_all_ranks(sm + SM_EXCH + rk * 32 + tid, p);
        }
        cluster_sync_();
        // --- H: xh += exch ---
        if (tid < 256) sm[SM_XH + tid] += sm[SM_EXCH + tid];
        __syncthreads();

        // --- DeltaNet layers ---
#pragma unroll
        for (int l = 0; l < 2; l++) {
            // I: qkv GEMV (tid<384: 12cg x 32iseg, 8 rows) + beta (warps 12-15)
            if (tid < 384) {
                int cg = tid % 12, iseg = tid / 12;
                const uint4* W = (const uint4*)(hs + WS_QKV) + (size_t)l * 3072 + cg;
                float a0=0,a1=0,a2=0,a3=0,a4=0,a5=0,a6=0,a7=0;
#pragma unroll
                for (int r = 0; r < 8; r++) {
                    int row = iseg + 32 * r;
                    float xv = sm[SM_XH + row];
                    uint4 w = W[row * 12];
                    FMA8(w, xv);
                }
                float* P = sm + SM_PART + iseg * 96 + cg * 8;
                P[0]=a0; P[1]=a1; P[2]=a2; P[3]=a3; P[4]=a4; P[5]=a5; P[6]=a6; P[7]=a7;
            } else {
                int c = (tid - 384) >> 5;
                const __half* Wb = hs + WS_BETA + l * 1024;
                float acc = 0.f;
#pragma unroll
                for (int j = 0; j < 8; j++) {
                    int row = la + 32 * j;
                    acc += sm[SM_XH + row] * __half2float(Wb[row * 4 + c]);
                }
#pragma unroll
                for (int o = 16; o > 0; o >>= 1) acc += __shfl_xor_sync(0xffffffffu, acc, o);
                if (la == 0) {
                    float z = acc + sm[SM_BBETA + l * 4 + c];
                    sm[SM_BETA + c] = 1.f / (1.f + expf(-z));
                }
            }
            __syncthreads();
            // J: reduce + exchange qkv cols
            if (tid < 96) {
                float p = sm[SM_BQKV2 + l * 96 + tid];
                for (int sg = 0; sg < 32; sg++) p += sm[SM_PART + sg * 96 + tid];
                bcast_all_ranks(sm + SM_QKV + rk * 96 + tid, p);
            }
            cluster_sync_();

            // K: k-norm + normalize (warp per head, tid<128)
            if (tid < 128) {
                int h = tid >> 5;
                float k0 = sm[SM_QKV + 256 + h * 64 + la];
                float k1 = sm[SM_QKV + 256 + h * 64 + 32 + la];
                float ss = k0 * k0 + k1 * k1;
#pragma unroll
                for (int o = 16; o > 0; o >>= 1) ss += __shfl_xor_sync(0xffffffffu, ss, o);
                float inv = 1.f / (sqrtf(ss) + 1e-6f);
                sm[SM_KHN + h * 64 + la] = k0 * inv;
                sm[SM_KHN + h * 64 + 32 + la] = k1 * inv;
            }
            __syncthreads();
            // M: state update (owners of layer l)
            if (l_own == l) {
                const float* kh = sm + SM_KHN + h_own * 64;
                const float* qh = sm + SM_QKV + h_own * 64;
                float sk = 0.f;
#pragma unroll
                for (int j = 0; j < 64; j++) sk += Sreg[j] * kh[j];
                float delta = sm[SM_BETA + h_own] * (sm[SM_QKV + 512 + h_own * 64 + i_own] - sk);
                float oacc = 0.f;
#pragma unroll
                for (int j = 0; j < 64; j++) { Sreg[j] += delta * kh[j]; oacc += Sreg[j] * qh[j]; }
                sm[SM_O + h_own * 64 + i_own] = oacc;
            }
            __syncthreads();
            // N: wo GEMV (tid<256: 4cg x 64iseg, 4 rows)
            if (tid < 256) {
                int cg = tid & 3, iseg = tid >> 2;
                const uint4* W = (const uint4*)(hs + WS_WO) + (size_t)l * 1024 + cg;
                float a0=0,a1=0,a2=0,a3=0,a4=0,a5=0,a6=0,a7=0;
#pragma unroll
                for (int r = 0; r < 4; r++) {
                    int row = iseg + 64 * r;
                    float xv = sm[SM_O + row];
                    uint4 w = W[row * 4];
                    FMA8(w, xv);
                }
                float* P = sm + SM_PART + iseg * 32 + cg * 8;
                P[0]=a0; P[1]=a1; P[2]=a2; P[3]=a3; P[4]=a4; P[5]=a5; P[6]=a6; P[7]=a7;
            }
            __syncthreads();
            // O: reduce + exchange
            if (tid < 32) {
                float p = sm[SM_BO2 + l * 32 + tid];
                for (int sg = 0; sg < 64; sg++) p += sm[SM_PART + sg * 32 + tid];
                bcast_all_ranks(sm + SM_WOUT + rk * 32 + tid, p);
            }
            cluster_sync_();
            // P: residual
            if (tid < 256) sm[SM_RESID + tid] = sm[SM_XH + tid] + sm[SM_WOUT + tid];
            __syncthreads();
            // Q: LN stats (warp 0)
            if (tid < 32) {
                float s1 = 0.f, s2 = 0.f;
#pragma unroll
                for (int k = 0; k < 8; k++) { float v = sm[SM_RESID + tid * 8 + k]; s1 += v; s2 += v * v; }
#pragma unroll
                for (int o = 16; o > 0; o >>= 1) {
                    s1 += __shfl_xor_sync(0xffffffffu, s1, o);
                    s2 += __shfl_xor_sync(0xffffffffu, s2, o);
                }
                if (tid == 0) {
                    float m = s1 / 256.f;
                    float var = s2 / 256.f - m * m;
                    sm[SM_MV + 0] = m; sm[SM_MV + 1] = rsqrtf(var + 1e-5f);
                }
            }
            __syncthreads();
            // R: normalize
            if (tid < 256)
                sm[SM_XH + tid] = (sm[SM_RESID + tid] - sm[SM_MV + 0]) * sm[SM_MV + 1]
                                * sm[SM_LNG + l * 256 + tid] + sm[SM_LNB + l * 256 + tid];
            __syncthreads();
        }

        // --- S: sup GEMV (tid<128: 2cg x 64iseg, 4 rows) + xh export (rk0) ---
        if (tid < 128) {
            int cg = tid & 1, iseg = tid >> 1;
            const uint4* W = (const uint4*)(hs + WS_SUP) + cg;
            float a0=0,a1=0,a2=0,a3=0,a4=0,a5=0,a6=0,a7=0;
#pragma unroll
            for (int r = 0; r < 4; r++) {
                int row = iseg + 64 * r;
                float xv = sm[SM_XH + row];
                uint4 w = W[row * 2];
                FMA8(w, xv);
            }
            float* P = sm + SM_PART + iseg * 16 + cg * 8;
            P[0]=a0; P[1]=a1; P[2]=a2; P[3]=a3; P[4]=a4; P[5]=a5; P[6]=a6; P[7]=a7;
        } else if (tid >= 256 && rk == 0) {
            g_rx[tok * 384 + 128 + (tid - 256)] = sm[SM_XH + tid - 256];
        }
        __syncthreads();
        // --- T: reduce + exchange u ---
        if (tid < 16) {
            float p = 0.f;
            for (int sg = 0; sg < 64; sg++) p += sm[SM_PART + sg * 16 + tid];
            bcast_all_ranks(sm + SM_U + rk * 16 + tid, p);
        }
        cluster_sync_();
        // --- U: fused final slot update ---
        for (int idx = tid; idx < Nv * SDv; idx += 512) {
            int n = idx >> 7, d = idx & 127;
            float sv = sm[SM_SLOTS + idx];
            sm[SM_SLOTS + idx] = sm[SM_C1 + n] * sv + sm[SM_C2 + n] * sm[SM_WR + d]
                               + sm[SM_T1 + n] * sm[SM_U + d] + sm[SM_G2 + n] * sm[SM_SUPB + d];
        }
        __syncthreads();
    }
}

// ---------------------------------------------------------------------------
// Kernel 3: ypre = read@sb_wo + xh@op_w + biases; out = LN(ypre) @ ow + ob.
// ---------------------------------------------------------------------------
__global__ __launch_bounds__(512) void k_out(
    const float* __restrict__ sb_wo, const float* __restrict__ sb_bo,
    const float* __restrict__ op_w, const float* __restrict__ op_b,
    const float* __restrict__ oln_g, const float* __restrict__ oln_b,
    const float* __restrict__ ow, const float* __restrict__ ob,
    float* __restrict__ out)
{
    __shared__ float rx[8 * 384];
    __shared__ float yt[8 * 512];
    __shared__ float mv[8][2];
    const int t0 = blockIdx.x * 8;
    const int tid = threadIdx.x;
    const float* src = g_rx + (size_t)t0 * 384;
    for (int idx = tid; idx < 8 * 384; idx += 512) rx[idx] = src[idx];
    __syncthreads();

    {
        float acc[8];
        float bias = sb_bo[tid] + op_b[tid];
#pragma unroll
        for (int t = 0; t < 8; t++) acc[t] = bias;
        const float* w1 = sb_wo + tid;
        for (int i = 0; i < 128; i++) {
            float wv = w1[(size_t)i * 512];
#pragma unroll
            for (int t = 0; t < 8; t++) acc[t] += rx[t * 384 + i] * wv;
        }
        const float* w2 = op_w + tid;
        for (int i = 0; i < 256; i++) {
            float wv = w2[(size_t)i * 512];
#pragma unroll
            for (int t = 0; t < 8; t++) acc[t] += rx[t * 384 + 128 + i] * wv;
        }
#pragma unroll
        for (int t = 0; t < 8; t++) yt[t * 512 + tid] = acc[t];
    }
    __syncthreads();

    if (tid < 256) {
        int tt = tid >> 5, lane = tid & 31;
        float s1 = 0.f, s2 = 0.f;
        for (int i = lane; i < 512; i += 32) { float v = yt[tt * 512 + i]; s1 += v; s2 += v * v; }
#pragma unroll
        for (int o = 16; o > 0; o >>= 1) {
            s1 += __shfl_xor_sync(0xffffffffu, s1, o);
            s2 += __shfl_xor_sync(0xffffffffu, s2, o);
        }
        if (lane == 0) {
            float m = s1 / 512.f;
            mv[tt][0] = m;
            mv[tt][1] = rsqrtf(s2 / 512.f - m * m + 1e-5f);
        }
    }
    __syncthreads();
    for (int idx = tid; idx < 8 * 512; idx += 512) {
        int tt = idx >> 9, c = idx & 511;
        yt[idx] = (yt[idx] - mv[tt][0]) * mv[tt][1] * oln_g[c] + oln_b[c];
    }
    __syncthreads();

    float acc[8];
#pragma unroll
    for (int t = 0; t < 8; t++) acc[t] = ob[tid];
    const float* w = ow + tid;
    for (int i = 0; i < 512; i++) {
        float wv = w[(size_t)i * 512];
#pragma unroll
        for (int t = 0; t < 8; t++) acc[t] += yt[t * 512 + i] * wv;
    }
    float* dst = out + (size_t)t0 * 512;
#pragma unroll
    for (int t = 0; t < 8; t++) dst[t * 512 + tid] = acc[t];
}

// ---------------------------------------------------------------------------
extern "C" void kernel_launch(void* const* d_in, const int* in_sizes, int n_in,
                              void* d_out, int out_size)
{
    const float* x        = (const float*)d_in[0];
    const float* sb_init  = (const float*)d_in[1];
    const float* sb_wq    = (const float*)d_in[2];
    const float* sb_bq    = (const float*)d_in[3];
    const float* sb_ww    = (const float*)d_in[4];
    const float* sb_bw    = (const float*)d_in[5];
    const float* sb_wo    = (const float*)d_in[6];
    const float* sb_bo    = (const float*)d_in[7];
    const float* p_win    = (const float*)d_in[8];
    const float* p_bin    = (const float*)d_in[9];
    const float* b_wq     = (const float*)d_in[10];
    const float* b_bq     = (const float*)d_in[11];
    const float* b_keys   = (const float*)d_in[12];
    const float* bp_w     = (const float*)d_in[13];
    const float* bp_b     = (const float*)d_in[14];
    const float* dn_wqkv  = (const float*)d_in[15];
    const float* dn_bqkv  = (const float*)d_in[16];
    const float* dn_wbeta = (const float*)d_in[17];
    const float* dn_bbeta = (const float*)d_in[18];
    const float* dn_wo    = (const float*)d_in[19];
    const float* dn_bo    = (const float*)d_in[20];
    const float* dn_lng   = (const float*)d_in[21];
    const float* dn_lnb   = (const float*)d_in[22];
    const float* sup_w    = (const float*)d_in[23];
    const float* sup_b    = (const float*)d_in[24];
    const float* op_w     = (const float*)d_in[25];
    const float* op_b     = (const float*)d_in[26];
    const float* oln_g    = (const float*)d_in[27];
    const float* oln_b    = (const float*)d_in[28];
    const float* ow       = (const float*)d_in[29];
    const float* ob       = (const float*)d_in[30];

    static bool attr_set = false;
    if (!attr_set) {
        cudaFuncSetAttribute(k_rec, cudaFuncAttributeMaxDynamicSharedMemorySize, SMEM_REC_BYTES);
        attr_set = true;
    }

    k_cvt<<<(H_TOTAL + 511) / 512, 512>>>(dn_wqkv, dn_wo, bp_w, sup_w, dn_wbeta);
    k_pre<<<512, 512>>>(x, sb_wq, sb_bq, sb_ww, sb_bw, p_win, p_bin);
    k_ba<<<1024, 256>>>(b_wq, b_bq, b_keys);
    k_rec<<<Bv * CLW, 512, SMEM_REC_BYTES>>>(sb_init, bp_b, dn_bqkv, dn_bbeta, dn_bo,
                                             dn_lng, dn_lnb, sup_b);
    k_out<<<1024, 512>>>(sb_wo, sb_bo, op_w, op_b, oln_g, oln_b, ow, ob, (float*)d_out);
}

// round 9
// speedup vs baseline: 4.4845x; 1.2892x over previous
#include <cuda_runtime.h>
#include <cuda_fp16.h>
#include <cstdint>
#include <math.h>

#define Bv 8
#define Sv 1024
#define Dv 512
#define Hv 256
#define Nv 64
#define SDv 128
#define NHv 4
#define DHv 64

#define CLW 8   // cluster width (ranks per batch)

// ---- device scratch (no allocations allowed) ----
__device__ float g_qwx[(size_t)Bv * Sv * 512];   // per token: [q(128) | wr(128) | xh0(256)]
__device__ float g_ba[(size_t)Bv * Sv * 64];     // precomputed attn2 softmax
__device__ float g_rx[(size_t)Bv * Sv * 384];    // per token: [read(128) | xh_final(256)]
__device__ __align__(256) __half g_h[591872];    // fp16 weight pack

#define H_QKV   0          // 2*256*768 = 393216
#define H_WO    393216     // 2*256*256 = 131072
#define H_BPW   524288     // 128*256   = 32768
#define H_SUPW  557056     // 256*128   = 32768
#define H_WBETA 589824     // 2*256*4   = 2048
#define H_TOTAL 591872

// smem float-index layout for k_rec
#define SM_SLOTS 0        // 8192
#define SM_PART  8192     // 3072
#define SM_Q     11264    // 128
#define SM_WR    11392    // 128
#define SM_XH    11520    // 256
#define SM_ABUF  11776    // 64
#define SM_A     11840    // 64
#define SM_BA    11904    // 64
#define SM_G2    11968    // 64
#define SM_CB    12032    // 64
#define SM_C1    12096    // 64
#define SM_C2    12160    // 64
#define SM_T1    12224    // 64
#define SM_BIND  12288    // 128
#define SM_QKV   12416    // 1536 = 2 sets x 768
#define SM_KHN   13952    // 256
#define SM_BETA  14208    // 4
#define SM_O     14212    // 256
#define SM_U     14468    // 256 = 2 x 128
#define SM_EXCH  14724    // 512 = 2 x 256
#define SM_WOUT  15236    // 512 = 2 x 256
#define SM_MV    15748    // 4
#define SM_BQKV2 15752    // 192
#define SM_BO2   15944    // 64
#define SM_LNG   16008    // 512
#define SM_LNB   16520    // 512
#define SM_BPB2  17032    // 32
#define SM_SUPB  17064    // 128
#define SM_BBETA 17192    // 8
#define SM_MBAR  17200    // 24 floats = 12 u64 mbarriers (byte 68800, 8B aligned)
#define SM_HBASE 17224    // halves start (byte 68896, 16B aligned)
// half offsets (relative to half base)
#define WS_QKV  0         // 2*256*96 = 49152
#define WS_WO   49152     // 2*256*32 = 16384
#define WS_BP   65536     // 128*32   = 4096
#define WS_SUP  69632     // 256*16   = 4096
#define WS_BETA 73728     // 2*256*4  = 2048
#define SMEM_REC_BYTES (SM_HBASE * 4 + 75776 * 2)   // 220448

// ---- cluster / mbarrier helpers ----
__device__ __forceinline__ void cluster_sync_() {
    asm volatile("barrier.cluster.arrive.aligned;" ::: "memory");
    asm volatile("barrier.cluster.wait.aligned;" ::: "memory");
}
__device__ __forceinline__ void mbar_init(float* lmbar, unsigned cnt) {
    unsigned m = (unsigned)__cvta_generic_to_shared(lmbar);
    asm volatile("mbarrier.init.shared.b64 [%0], %1;" :: "r"(m), "r"(cnt) : "memory");
}
__device__ __forceinline__ void mbar_expect(float* lmbar, unsigned tx) {
    unsigned m = (unsigned)__cvta_generic_to_shared(lmbar);
    asm volatile("mbarrier.arrive.expect_tx.shared.b64 _, [%0], %1;" :: "r"(m), "r"(tx) : "memory");
}
// bounded-spin wait: never hangs the container; on (never-expected) timeout we
// proceed, which surfaces as a correctness failure instead of a hung bench.
__device__ __forceinline__ void mbar_wait(float* lmbar, unsigned parity) {
    unsigned m = (unsigned)__cvta_generic_to_shared(lmbar);
    unsigned done = 0;
    long long t0 = clock64();
    while (!done) {
        asm volatile("{\n\t.reg .pred P;\n\t"
            "mbarrier.try_wait.parity.acquire.cluster.shared::cta.b64 P, [%1], %2, 0x989680;\n\t"
            "selp.b32 %0, 1, 0, P;\n\t}"
            : "=r"(done) : "r"(m), "r"(parity) : "memory");
        if (!done && (clock64() - t0) > 200000000LL) break;   // ~0.1 s watchdog
    }
}
// remote store of one f32 + tx-signal on remote mbarrier (rank rr)
__device__ __forceinline__ void st_async_f32(float* lptr, float* lmbar, int rr, float v) {
    unsigned a = (unsigned)__cvta_generic_to_shared(lptr);
    unsigned m = (unsigned)__cvta_generic_to_shared(lmbar);
    unsigned ra, rm;
    asm volatile("mapa.shared::cluster.u32 %0, %1, %2;" : "=r"(ra) : "r"(a), "r"(rr));
    asm volatile("mapa.shared::cluster.u32 %0, %1, %2;" : "=r"(rm) : "r"(m), "r"(rr));
    asm volatile("st.async.shared::cluster.mbarrier::complete_tx::bytes.b32 [%0], %1, [%2];"
                 :: "r"(ra), "r"(__float_as_uint(v)), "r"(rm) : "memory");
}
__device__ __forceinline__ void bcast_async(float* lptr, float* lmbar, float v) {
#pragma unroll
    for (int rr = 0; rr < CLW; rr++) st_async_f32(lptr, lmbar, rr, v);
}

// fp16 vec8 FMA helper
#define FMA8(w, xv) do { \
    half2 h0 = *(half2*)&(w).x, h1 = *(half2*)&(w).y, h2 = *(half2*)&(w).z, h3 = *(half2*)&(w).w; \
    a0 += (xv) * __low2float(h0); a1 += (xv) * __high2float(h0); \
    a2 += (xv) * __low2float(h1); a3 += (xv) * __high2float(h1); \
    a4 += (xv) * __low2float(h2); a5 += (xv) * __high2float(h2); \
    a6 += (xv) * __low2float(h3); a7 += (xv) * __high2float(h3); } while (0)

// ---------------------------------------------------------------------------
__global__ __launch_bounds__(512) void k_cvt(
    const float* __restrict__ wqkv, const float* __restrict__ wo,
    const float* __restrict__ bpw, const float* __restrict__ supw,
    const float* __restrict__ wbeta)
{
    int i = blockIdx.x * 512 + threadIdx.x;
    if (i >= H_TOTAL) return;
    float v;
    if (i < H_WO)        v = wqkv[i];
    else if (i < H_BPW)  v = wo[i - H_WO];
    else if (i < H_SUPW) v = bpw[i - H_BPW];
    else if (i < H_WBETA) v = supw[i - H_SUPW];
    else                 v = wbeta[i - H_WBETA];
    g_h[i] = __float2half(v);
}

// ---------------------------------------------------------------------------
__global__ __launch_bounds__(512) void k_pre(
    const float* __restrict__ x,
    const float* __restrict__ sb_wq, const float* __restrict__ sb_bq,
    const float* __restrict__ sb_ww, const float* __restrict__ sb_bw,
    const float* __restrict__ p_win, const float* __restrict__ p_bin)
{
    __shared__ float xs[16 * 512];
    const int t0 = blockIdx.x * 16;
    const int tid = threadIdx.x;
    const float* xb = x + (size_t)t0 * 512;
    for (int idx = tid; idx < 16 * 512; idx += 512) xs[idx] = xb[idx];
    __syncthreads();

    const int c = tid;
    const float* W; int ld; float bias;
    if (c < 128)      { W = sb_wq + c;         ld = 128; bias = sb_bq[c]; }
    else if (c < 256) { W = sb_ww + (c - 128); ld = 128; bias = sb_bw[c - 128]; }
    else              { W = p_win + (c - 256); ld = 256; bias = p_bin[c - 256]; }

    float acc[16];
#pragma unroll
    for (int t = 0; t < 16; t++) acc[t] = 0.f;
    for (int i = 0; i < 512; i++) {
        float w = W[(size_t)i * ld];
#pragma unroll
        for (int t = 0; t < 16; t++) acc[t] += xs[t * 512 + i] * w;
    }
#pragma unroll
    for (int t = 0; t < 16; t++)
        g_qwx[((size_t)(t0 + t)) * 512 + c] = acc[t] + bias;
}

// ---------------------------------------------------------------------------
__global__ __launch_bounds__(256) void k_ba(
    const float* __restrict__ b_wq, const float* __restrict__ b_bq,
    const float* __restrict__ b_keys)
{
    __shared__ float s_x[8 * 256];
    __shared__ float s_keys[64 * 129];
    __shared__ float s_bq[8 * 128];
    const int t0 = blockIdx.x * 8;
    const int tid = threadIdx.x;

    for (int idx = tid; idx < 8 * 256; idx += 256) {
        int t = idx >> 8, i = idx & 255;
        s_x[idx] = g_qwx[((size_t)(t0 + t)) * 512 + 256 + i];
    }
    for (int idx = tid; idx < 64 * 128; idx += 256) {
        int n = idx >> 7, k = idx & 127;
        s_keys[n * 129 + k] = b_keys[idx];
    }
    __syncthreads();

    {
        int c = tid & 127, tg = tid >> 7;
        float acc[4];
        float bb = b_bq[c];
#pragma unroll
        for (int t = 0; t < 4; t++) acc[t] = bb;
        for (int i = 0; i < 256; i++) {
            float w = b_wq[i * 128 + c];
#pragma unroll
            for (int t = 0; t < 4; t++) acc[t] += s_x[(tg * 4 + t) * 256 + i] * w;
        }
#pragma unroll
        for (int t = 0; t < 4; t++) s_bq[(tg * 4 + t) * 128 + c] = acc[t];
    }
    __syncthreads();

    {
        const float invscale = 0.08838834764831845f;
        int t = tid >> 5, lane = tid & 31;
        float l0 = 0.f, l1 = 0.f;
        for (int k = 0; k < 128; k++) {
            float q = s_bq[t * 128 + k];
            l0 += q * s_keys[lane * 129 + k];
            l1 += q * s_keys[(lane + 32) * 129 + k];
        }
        l0 *= invscale; l1 *= invscale;
        float m = fmaxf(l0, l1);
#pragma unroll
        for (int o = 16; o > 0; o >>= 1) m = fmaxf(m, __shfl_xor_sync(0xffffffffu, m, o));
        float e0 = expf(l0 - m), e1 = expf(l1 - m);
        float ssum = e0 + e1;
#pragma unroll
        for (int o = 16; o > 0; o >>= 1) ssum += __shfl_xor_sync(0xffffffffu, ssum, o);
        float inv = 1.f / ssum;
        float* dst = g_ba + ((size_t)(t0 + t)) * 64;
        dst[lane] = e0 * inv;
        dst[lane + 32] = e1 * inv;
    }
}

// ---------------------------------------------------------------------------
// Kernel 2: recurrent core. 64 CTAs = 8 batches x cluster of 8.
// SMEM-resident weight slices; st.async + mbarrier exchange (double-buffered).
// ---------------------------------------------------------------------------
__global__ __launch_bounds__(512, 1) __cluster_dims__(CLW, 1, 1)
void k_rec(
    const float* __restrict__ sb_init, const float* __restrict__ bp_b,
    const float* __restrict__ dn_bqkv, const float* __restrict__ dn_bbeta,
    const float* __restrict__ dn_bo, const float* __restrict__ dn_lng,
    const float* __restrict__ dn_lnb, const float* __restrict__ sup_b)
{
    extern __shared__ float sm[];
    __half* hs = (__half*)(sm + SM_HBASE);

    const int tid = threadIdx.x;
    const int b  = blockIdx.x / CLW;
    const int rk = blockIdx.x % CLW;
    const float invscale = 0.08838834764831845f;

    // ---- one-time init ----
    for (int idx = tid; idx < Nv * SDv; idx += 512) sm[SM_SLOTS + idx] = sb_init[idx];
    if (tid < 192) sm[SM_BQKV2 + tid] = dn_bqkv[(tid / 96) * 768 + rk * 96 + (tid % 96)];
    if (tid < 64)  sm[SM_BO2 + tid]   = dn_bo[(tid / 32) * 256 + rk * 32 + (tid % 32)];
    if (tid < 512) { sm[SM_LNG + tid] = dn_lng[tid]; sm[SM_LNB + tid] = dn_lnb[tid]; }
    if (tid < 32)  sm[SM_BPB2 + tid]  = bp_b[rk * 32 + tid];
    if (tid < 128) sm[SM_SUPB + tid]  = sup_b[tid];
    if (tid < 8)   sm[SM_BBETA + tid] = dn_bbeta[tid];
    if (tid == 0) {
        for (int i = 0; i < 12; i++) mbar_init(sm + SM_MBAR + i * 2, 1u);
    }

    {   // qkv slice: 6144 uint4
        const uint4* src = (const uint4*)(g_h + H_QKV);
        uint4* dst = (uint4*)(hs + WS_QKV);
        for (int i = tid; i < 6144; i += 512) {
            int rowL = i / 12, c = i % 12;
            dst[rowL * 12 + c] = src[(size_t)rowL * 96 + rk * 12 + c];
        }
    }
    {   // wo slice: 2048 uint4
        const uint4* src = (const uint4*)(g_h + H_WO);
        uint4* dst = (uint4*)(hs + WS_WO);
        for (int i = tid; i < 2048; i += 512) {
            int rowL = i / 4, c = i % 4;
            dst[rowL * 4 + c] = src[(size_t)rowL * 32 + rk * 4 + c];
        }
    }
    {   // bp slice: 512 uint4
        const uint4* src = (const uint4*)(g_h + H_BPW);
        uint4* dst = (uint4*)(hs + WS_BP);
        for (int i = tid; i < 512; i += 512) {
            int row = i / 4, c = i % 4;
            dst[row * 4 + c] = src[(size_t)row * 32 + rk * 4 + c];
        }
    }
    {   // sup slice: 512 uint4
        const uint4* src = (const uint4*)(g_h + H_SUPW);
        uint4* dst = (uint4*)(hs + WS_SUP);
        for (int i = tid; i < 512; i += 512) {
            int row = i / 2, c = i % 2;
            dst[row * 2 + c] = src[(size_t)row * 16 + rk * 2 + c];
        }
    }
    {   // wbeta replicated: 256 uint4
        const uint4* src = (const uint4*)(g_h + H_WBETA);
        uint4* dst = (uint4*)(hs + WS_BETA);
        for (int i = tid; i < 256; i += 512) dst[i] = src[i];
    }

    float Sreg[64];
#pragma unroll
    for (int j = 0; j < 64; j++) Sreg[j] = 0.f;
    const int l_own = tid >> 8;
    const int h_own = (tid >> 6) & 3;
    const int i_own = tid & 63;
    const int wp = tid >> 5, la = tid & 31;
    __syncthreads();
    cluster_sync_();   // mbarrier init visible cluster-wide

    // token prefetch registers (step 0)
    float pf_q = g_qwx[(size_t)(b * Sv) * 512 + tid];
    float pf_b = (tid < 64) ? g_ba[(size_t)(b * Sv) * 64 + tid] : 0.f;

    for (int s = 0; s < Sv; ++s) {
        const size_t tok = (size_t)(b * Sv + s);
        const int set = s & 1;
        const unsigned par = (unsigned)((s >> 1) & 1);
        float* MB = sm + SM_MBAR + set * 2;   // barriers i at MB + i*4

        // --- arm this step's barriers (tid 0) ---
        if (tid == 0) {
            mbar_expect(MB + 0 * 4, 1024u);   // bp
            mbar_expect(MB + 1 * 4, 3072u);   // qkv l0
            mbar_expect(MB + 2 * 4, 1024u);   // wo  l0
            mbar_expect(MB + 3 * 4, 3072u);   // qkv l1
            mbar_expect(MB + 4 * 4, 1024u);   // wo  l1
            mbar_expect(MB + 5 * 4, 512u);    // u
        }

        // --- A: commit prefetched token data ---
        if (tid < 128) sm[SM_Q + tid] = pf_q;
        else if (tid < 256) sm[SM_WR + tid - 128] = pf_q;
        else sm[SM_XH + tid - 256] = pf_q;
        if (tid < 64) {
            sm[SM_BA + tid] = pf_b;
            sm[SM_G2 + tid] = 1.f / (1.f + expf(-pf_b));
        }
        __syncthreads();
        // prefetch next token
        if (s + 1 < Sv) {
            pf_q = g_qwx[(tok + 1) * 512 + tid];
            if (tid < 64) pf_b = g_ba[(tok + 1) * 64 + tid];
        }

        // --- B: attn1 logits ---
#pragma unroll
        for (int r = 0; r < 4; r++) {
            int n = wp * 4 + r;
            const float* row = sm + SM_SLOTS + n * 128;
            float p = row[la] * sm[SM_Q + la] + row[la + 32] * sm[SM_Q + la + 32]
                    + row[la + 64] * sm[SM_Q + la + 64] + row[la + 96] * sm[SM_Q + la + 96];
#pragma unroll
            for (int o = 16; o > 0; o >>= 1) p += __shfl_xor_sync(0xffffffffu, p, o);
            if (la == 0) sm[SM_ABUF + n] = p * invscale;
        }
        __syncthreads();

        // --- C: softmax + per-n coefficients (warp 0) ---
        if (tid < 32) {
            float l0 = sm[SM_ABUF + tid], l1 = sm[SM_ABUF + tid + 32];
            float m = fmaxf(l0, l1);
#pragma unroll
            for (int o = 16; o > 0; o >>= 1) m = fmaxf(m, __shfl_xor_sync(0xffffffffu, m, o));
            float e0 = expf(l0 - m), e1 = expf(l1 - m);
            float ss = e0 + e1;
#pragma unroll
            for (int o = 16; o > 0; o >>= 1) ss += __shfl_xor_sync(0xffffffffu, ss, o);
            float inv = 1.f / ss;
            float a0 = e0 * inv, a1 = e1 * inv;
            float g0 = 1.f / (1.f + expf(-a0)), g1 = 1.f / (1.f + expf(-a1));
            float ba0 = sm[SM_BA + tid], ba1 = sm[SM_BA + tid + 32];
            float g20 = sm[SM_G2 + tid], g21 = sm[SM_G2 + tid + 32];
            sm[SM_A + tid] = a0;  sm[SM_A + tid + 32] = a1;
            sm[SM_CB + tid] = ba0 * (1.f - g0);         sm[SM_CB + tid + 32] = ba1 * (1.f - g1);
            sm[SM_C1 + tid] = (1.f - g20) * (1.f - g0); sm[SM_C1 + tid + 32] = (1.f - g21) * (1.f - g1);
            sm[SM_C2 + tid] = (1.f - g20) * g0 * a0;    sm[SM_C2 + tid + 32] = (1.f - g21) * g1 * a1;
            sm[SM_T1 + tid] = g20 * ba0;                sm[SM_T1 + tid + 32] = g21 * ba1;
            float cw = ba0 * g0 * a0 + ba1 * g1 * a1;
#pragma unroll
            for (int o = 16; o > 0; o >>= 1) cw += __shfl_xor_sync(0xffffffffu, cw, o);
            if (tid == 0) sm[SM_MV + 2] = cw;
        }
        __syncthreads();

        // --- D: fused read+bind partials ---
        {
            int d = tid & 127, ch = tid >> 7;
            float pr0 = 0.f, pr1 = 0.f, pb0 = 0.f, pb1 = 0.f;
#pragma unroll
            for (int k = 0; k < 16; k += 2) {
                int n0 = ch * 16 + k, n1 = n0 + 1;
                float sv0 = sm[SM_SLOTS + n0 * 128 + d];
                float sv1 = sm[SM_SLOTS + n1 * 128 + d];
                pr0 += sm[SM_A + n0] * sv0;  pr1 += sm[SM_A + n1] * sv1;
                pb0 += sm[SM_CB + n0] * sv0; pb1 += sm[SM_CB + n1] * sv1;
            }
            sm[SM_PART + ch * 128 + d] = pr0 + pr1;
            sm[SM_PART + 512 + ch * 128 + d] = pb0 + pb1;
        }
        __syncthreads();
        // --- E: reduce read (export) + bind ---
        if (tid < 128) {
            float rv = sm[SM_PART + tid] + sm[SM_PART + 128 + tid]
                     + sm[SM_PART + 256 + tid] + sm[SM_PART + 384 + tid];
            if (rk == 0) g_rx[tok * 384 + tid] = rv;
            float bv = (sm[SM_PART + 512 + tid] + sm[SM_PART + 640 + tid])
                     + (sm[SM_PART + 768 + tid] + sm[SM_PART + 896 + tid])
                     + sm[SM_MV + 2] * sm[SM_WR + tid];
            sm[SM_BIND + tid] = bv;
        }
        __syncthreads();

        // --- F: bp GEMV ---
        if (tid < 128) {
            int cg = tid & 3, iseg = tid >> 2;
            const uint4* W = (const uint4*)(hs + WS_BP) + cg;
            float a0=0,a1=0,a2=0,a3=0,a4=0,a5=0,a6=0,a7=0;
#pragma unroll
            for (int r = 0; r < 4; r++) {
                int row = iseg + 32 * r;
                float xv = sm[SM_BIND + row];
                uint4 w = W[row * 4];
                FMA8(w, xv);
            }
            float* P = sm + SM_PART + iseg * 32 + cg * 8;
            P[0]=a0; P[1]=a1; P[2]=a2; P[3]=a3; P[4]=a4; P[5]=a5; P[6]=a6; P[7]=a7;
        }
        __syncthreads();
        // --- G: reduce + async exchange ---
        if (tid < 32) {
            float p0 = sm[SM_BPB2 + tid], p1 = 0.f, p2 = 0.f, p3 = 0.f;
#pragma unroll
            for (int sg = 0; sg < 32; sg += 4) {
                p0 += sm[SM_PART + sg * 32 + tid];
                p1 += sm[SM_PART + (sg + 1) * 32 + tid];
                p2 += sm[SM_PART + (sg + 2) * 32 + tid];
                p3 += sm[SM_PART + (sg + 3) * 32 + tid];
            }
            bcast_async(sm + SM_EXCH + set * 256 + rk * 32 + tid, MB + 0 * 4, (p0 + p1) + (p2 + p3));
        }
        mbar_wait(MB + 0 * 4, par);
        // --- H: xh += exch ---
        if (tid < 256) sm[SM_XH + tid] += sm[SM_EXCH + set * 256 + tid];
        __syncthreads();

        // --- DeltaNet layers ---
#pragma unroll
        for (int l = 0; l < 2; l++) {
            // I: qkv GEMV + beta
            if (tid < 384) {
                int cg = tid % 12, iseg = tid / 12;
                const uint4* W = (const uint4*)(hs + WS_QKV) + (size_t)l * 3072 + cg;
                float a0=0,a1=0,a2=0,a3=0,a4=0,a5=0,a6=0,a7=0;
#pragma unroll
                for (int r = 0; r < 8; r++) {
                    int row = iseg + 32 * r;
                    float xv = sm[SM_XH + row];
                    uint4 w = W[row * 12];
                    FMA8(w, xv);
                }
                float* P = sm + SM_PART + iseg * 96 + cg * 8;
                P[0]=a0; P[1]=a1; P[2]=a2; P[3]=a3; P[4]=a4; P[5]=a5; P[6]=a6; P[7]=a7;
            } else {
                int c = (tid - 384) >> 5;
                const __half* Wb = hs + WS_BETA + l * 1024;
                float acc = 0.f;
#pragma unroll
                for (int j = 0; j < 8; j++) {
                    int row = la + 32 * j;
                    acc += sm[SM_XH + row] * __half2float(Wb[row * 4 + c]);
                }
#pragma unroll
                for (int o = 16; o > 0; o >>= 1) acc += __shfl_xor_sync(0xffffffffu, acc, o);
                if (la == 0) {
                    float z = acc + sm[SM_BBETA + l * 4 + c];
                    sm[SM_BETA + c] = 1.f / (1.f + expf(-z));
                }
            }
            __syncthreads();
            // J: reduce + async exchange qkv
            if (tid < 96) {
                float p0 = sm[SM_BQKV2 + l * 96 + tid], p1 = 0.f, p2 = 0.f, p3 = 0.f;
#pragma unroll
                for (int sg = 0; sg < 32; sg += 4) {
                    p0 += sm[SM_PART + sg * 96 + tid];
                    p1 += sm[SM_PART + (sg + 1) * 96 + tid];
                    p2 += sm[SM_PART + (sg + 2) * 96 + tid];
                    p3 += sm[SM_PART + (sg + 3) * 96 + tid];
                }
                bcast_async(sm + SM_QKV + set * 768 + rk * 96 + tid, MB + (1 + 2 * l) * 4, (p0 + p1) + (p2 + p3));
            }
            mbar_wait(MB + (1 + 2 * l) * 4, par);
            const float* qkvb = sm + SM_QKV + set * 768;

            // K: k-norm + normalize (warp per head)
            if (tid < 128) {
                int h = tid >> 5;
                float k0 = qkvb[256 + h * 64 + la];
                float k1 = qkvb[256 + h * 64 + 32 + la];
                float ss = k0 * k0 + k1 * k1;
#pragma unroll
                for (int o = 16; o > 0; o >>= 1) ss += __shfl_xor_sync(0xffffffffu, ss, o);
                float inv = 1.f / (sqrtf(ss) + 1e-6f);
                sm[SM_KHN + h * 64 + la] = k0 * inv;
                sm[SM_KHN + h * 64 + 32 + la] = k1 * inv;
            }
            __syncthreads();
            // M: state update (owners of layer l)
            if (l_own == l) {
                const float* kh = sm + SM_KHN + h_own * 64;
                const float* qh = qkvb + h_own * 64;
                float s0 = 0.f, s1 = 0.f, s2 = 0.f, s3 = 0.f;
#pragma unroll
                for (int j = 0; j < 64; j += 4) {
                    s0 += Sreg[j] * kh[j];     s1 += Sreg[j + 1] * kh[j + 1];
                    s2 += Sreg[j + 2] * kh[j + 2]; s3 += Sreg[j + 3] * kh[j + 3];
                }
                float sk = (s0 + s1) + (s2 + s3);
                float delta = sm[SM_BETA + h_own] * (qkvb[512 + h_own * 64 + i_own] - sk);
                float o0 = 0.f, o1 = 0.f, o2 = 0.f, o3 = 0.f;
#pragma unroll
                for (int j = 0; j < 64; j += 4) {
                    Sreg[j]     += delta * kh[j];     o0 += Sreg[j] * qh[j];
                    Sreg[j + 1] += delta * kh[j + 1]; o1 += Sreg[j + 1] * qh[j + 1];
                    Sreg[j + 2] += delta * kh[j + 2]; o2 += Sreg[j + 2] * qh[j + 2];
                    Sreg[j + 3] += delta * kh[j + 3]; o3 += Sreg[j + 3] * qh[j + 3];
                }
                sm[SM_O + h_own * 64 + i_own] = (o0 + o1) + (o2 + o3);
            }
            __syncthreads();
            // N: wo GEMV
            if (tid < 256) {
                int cg = tid & 3, iseg = tid >> 2;
                const uint4* W = (const uint4*)(hs + WS_WO) + (size_t)l * 1024 + cg;
                float a0=0,a1=0,a2=0,a3=0,a4=0,a5=0,a6=0,a7=0;
#pragma unroll
                for (int r = 0; r < 4; r++) {
                    int row = iseg + 64 * r;
                    float xv = sm[SM_O + row];
                    uint4 w = W[row * 4];
                    FMA8(w, xv);
                }
                float* P = sm + SM_PART + iseg * 32 + cg * 8;
                P[0]=a0; P[1]=a1; P[2]=a2; P[3]=a3; P[4]=a4; P[5]=a5; P[6]=a6; P[7]=a7;
            }
            __syncthreads();
            // O: reduce + async exchange
            if (tid < 32) {
                float p0 = sm[SM_BO2 + l * 32 + tid], p1 = 0.f, p2 = 0.f, p3 = 0.f;
#pragma unroll
                for (int sg = 0; sg < 64; sg += 4) {
                    p0 += sm[SM_PART + sg * 32 + tid];
                    p1 += sm[SM_PART + (sg + 1) * 32 + tid];
                    p2 += sm[SM_PART + (sg + 2) * 32 + tid];
                    p3 += sm[SM_PART + (sg + 3) * 32 + tid];
                }
                bcast_async(sm + SM_WOUT + set * 256 + rk * 32 + tid, MB + (2 + 2 * l) * 4, (p0 + p1) + (p2 + p3));
            }
            mbar_wait(MB + (2 + 2 * l) * 4, par);
            const float* woutb = sm + SM_WOUT + set * 256;

            // Q: LN stats from xh+wout (warp 0)
            if (tid < 32) {
                float s1 = 0.f, s2 = 0.f;
#pragma unroll
                for (int k = 0; k < 8; k++) {
                    float v = sm[SM_XH + tid * 8 + k] + woutb[tid * 8 + k];
                    s1 += v; s2 += v * v;
                }
#pragma unroll
                for (int o = 16; o > 0; o >>= 1) {
                    s1 += __shfl_xor_sync(0xffffffffu, s1, o);
                    s2 += __shfl_xor_sync(0xffffffffu, s2, o);
                }
                if (tid == 0) {
                    float m = s1 / 256.f;
                    float var = s2 / 256.f - m * m;
                    sm[SM_MV + 0] = m; sm[SM_MV + 1] = rsqrtf(var + 1e-5f);
                }
            }
            __syncthreads();
            // R: normalize (resid recomputed inline)
            if (tid < 256) {
                float r = sm[SM_XH + tid] + woutb[tid];
                sm[SM_XH + tid] = (r - sm[SM_MV + 0]) * sm[SM_MV + 1]
                                * sm[SM_LNG + l * 256 + tid] + sm[SM_LNB + l * 256 + tid];
            }
            __syncthreads();
        }

        // --- S: sup GEMV + xh export (rk0) ---
        if (tid < 128) {
            int cg = tid & 1, iseg = tid >> 1;
            const uint4* W = (const uint4*)(hs + WS_SUP) + cg;
            float a0=0,a1=0,a2=0,a3=0,a4=0,a5=0,a6=0,a7=0;
#pragma unroll
            for (int r = 0; r < 4; r++) {
                int row = iseg + 64 * r;
                float xv = sm[SM_XH + row];
                uint4 w = W[row * 2];
                FMA8(w, xv);
            }
            float* P = sm + SM_PART + iseg * 16 + cg * 8;
            P[0]=a0; P[1]=a1; P[2]=a2; P[3]=a3; P[4]=a4; P[5]=a5; P[6]=a6; P[7]=a7;
        } else if (tid >= 256 && rk == 0) {
            g_rx[tok * 384 + 128 + (tid - 256)] = sm[SM_XH + tid - 256];
        }
        __syncthreads();
        // --- T: reduce + async exchange u ---
        if (tid < 16) {
            float p0 = 0.f, p1 = 0.f, p2 = 0.f, p3 = 0.f;
#pragma unroll
            for (int sg = 0; sg < 64; sg += 4) {
                p0 += sm[SM_PART + sg * 16 + tid];
                p1 += sm[SM_PART + (sg + 1) * 16 + tid];
                p2 += sm[SM_PART + (sg + 2) * 16 + tid];
                p3 += sm[SM_PART + (sg + 3) * 16 + tid];
            }
            bcast_async(sm + SM_U + set * 128 + rk * 16 + tid, MB + 5 * 4, (p0 + p1) + (p2 + p3));
        }
        mbar_wait(MB + 5 * 4, par);
        // --- U: fused final slot update ---
        {
            const float* ub = sm + SM_U + set * 128;
            for (int idx = tid; idx < Nv * SDv; idx += 512) {
                int n = idx >> 7, d = idx & 127;
                float sv = sm[SM_SLOTS + idx];
                sm[SM_SLOTS + idx] = sm[SM_C1 + n] * sv + sm[SM_C2 + n] * sm[SM_WR + d]
                                   + sm[SM_T1 + n] * ub[d] + sm[SM_G2 + n] * sm[SM_SUPB + d];
            }
        }
        __syncthreads();
    }
    cluster_sync_();   // keep cluster resident until all remote stores landed
}

// ---------------------------------------------------------------------------
__global__ __launch_bounds__(512) void k_out(
    const float* __restrict__ sb_wo, const float* __restrict__ sb_bo,
    const float* __restrict__ op_w, const float* __restrict__ op_b,
    const float* __restrict__ oln_g, const float* __restrict__ oln_b,
    const float* __restrict__ ow, const float* __restrict__ ob,
    float* __restrict__ out)
{
    __shared__ float rx[8 * 384];
    __shared__ float yt[8 * 512];
    __shared__ float mv[8][2];
    const int t0 = blockIdx.x * 8;
    const int tid = threadIdx.x;
    const float* src = g_rx + (size_t)t0 * 384;
    for (int idx = tid; idx < 8 * 384; idx += 512) rx[idx] = src[idx];
    __syncthreads();

    {
        float acc[8];
        float bias = sb_bo[tid] + op_b[tid];
#pragma unroll
        for (int t = 0; t < 8; t++) acc[t] = bias;
        const float* w1 = sb_wo + tid;
        for (int i = 0; i < 128; i++) {
            float wv = w1[(size_t)i * 512];
#pragma unroll
            for (int t = 0; t < 8; t++) acc[t] += rx[t * 384 + i] * wv;
        }
        const float* w2 = op_w + tid;
        for (int i = 0; i < 256; i++) {
            float wv = w2[(size_t)i * 512];
#pragma unroll
            for (int t = 0; t < 8; t++) acc[t] += rx[t * 384 + 128 + i] * wv;
        }
#pragma unroll
        for (int t = 0; t < 8; t++) yt[t * 512 + tid] = acc[t];
    }
    __syncthreads();

    if (tid < 256) {
        int tt = tid >> 5, lane = tid & 31;
        float s1 = 0.f, s2 = 0.f;
        for (int i = lane; i < 512; i += 32) { float v = yt[tt * 512 + i]; s1 += v; s2 += v * v; }
#pragma unroll
        for (int o = 16; o > 0; o >>= 1) {
            s1 += __shfl_xor_sync(0xffffffffu, s1, o);
            s2 += __shfl_xor_sync(0xffffffffu, s2, o);
        }
        if (lane == 0) {
            float m = s1 / 512.f;
            mv[tt][0] = m;
            mv[tt][1] = rsqrtf(s2 / 512.f - m * m + 1e-5f);
        }
    }
    __syncthreads();
    for (int idx = tid; idx < 8 * 512; idx += 512) {
        int tt = idx >> 9, c = idx & 511;
        yt[idx] = (yt[idx] - mv[tt][0]) * mv[tt][1] * oln_g[c] + oln_b[c];
    }
    __syncthreads();

    float acc[8];
#pragma unroll
    for (int t = 0; t < 8; t++) acc[t] = ob[tid];
    const float* w = ow + tid;
    for (int i = 0; i < 512; i++) {
        float wv = w[(size_t)i * 512];
#pragma unroll
        for (int t = 0; t < 8; t++) acc[t] += yt[t * 512 + i] * wv;
    }
    float* dst = out + (size_t)t0 * 512;
#pragma unroll
    for (int t = 0; t < 8; t++) dst[t * 512 + tid] = acc[t];
}

// ---------------------------------------------------------------------------
extern "C" void kernel_launch(void* const* d_in, const int* in_sizes, int n_in,
                              void* d_out, int out_size)
{
    const float* x        = (const float*)d_in[0];
    const float* sb_init  = (const float*)d_in[1];
    const float* sb_wq    = (const float*)d_in[2];
    const float* sb_bq    = (const float*)d_in[3];
    const float* sb_ww    = (const float*)d_in[4];
    const float* sb_bw    = (const float*)d_in[5];
    const float* sb_wo    = (const float*)d_in[6];
    const float* sb_bo    = (const float*)d_in[7];
    const float* p_win    = (const float*)d_in[8];
    const float* p_bin    = (const float*)d_in[9];
    const float* b_wq     = (const float*)d_in[10];
    const float* b_bq     = (const float*)d_in[11];
    const float* b_keys   = (const float*)d_in[12];
    const float* bp_w     = (const float*)d_in[13];
    const float* bp_b     = (const float*)d_in[14];
    const float* dn_wqkv  = (const float*)d_in[15];
    const float* dn_bqkv  = (const float*)d_in[16];
    const float* dn_wbeta = (const float*)d_in[17];
    const float* dn_bbeta = (const float*)d_in[18];
    const float* dn_wo    = (const float*)d_in[19];
    const float* dn_bo    = (const float*)d_in[20];
    const float* dn_lng   = (const float*)d_in[21];
    const float* dn_lnb   = (const float*)d_in[22];
    const float* sup_w    = (const float*)d_in[23];
    const float* sup_b    = (const float*)d_in[24];
    const float* op_w     = (const float*)d_in[25];
    const float* op_b     = (const float*)d_in[26];
    const float* oln_g    = (const float*)d_in[27];
    const float* oln_b    = (const float*)d_in[28];
    const float* ow       = (const float*)d_in[29];
    const float* ob       = (const float*)d_in[30];

    static bool attr_set = false;
    if (!attr_set) {
        cudaFuncSetAttribute(k_rec, cudaFuncAttributeMaxDynamicSharedMemorySize, SMEM_REC_BYTES);
        attr_set = true;
    }

    k_cvt<<<(H_TOTAL + 511) / 512, 512>>>(dn_wqkv, dn_wo, bp_w, sup_w, dn_wbeta);
    k_pre<<<512, 512>>>(x, sb_wq, sb_bq, sb_ww, sb_bw, p_win, p_bin);
    k_ba<<<1024, 256>>>(b_wq, b_bq, b_keys);
    k_rec<<<Bv * CLW, 512, SMEM_REC_BYTES>>>(sb_init, bp_b, dn_bqkv, dn_bbeta, dn_bo,
                                             dn_lng, dn_lnb, sup_b);
    k_out<<<1024, 512>>>(sb_wo, sb_bo, op_w, op_b, oln_g, oln_b, ow, ob, (float*)d_out);
}

// round 10
// speedup vs baseline: 4.7799x; 1.0659x over previous
#include <cuda_runtime.h>
#include <cuda_fp16.h>
#include <cstdint>
#include <math.h>

#define Bv 8
#define Sv 1024
#define Dv 512
#define Hv 256
#define Nv 64
#define SDv 128
#define NHv 4
#define DHv 64

#define CLW 8   // cluster width (ranks per batch)

// ---- device scratch (no allocations allowed) ----
__device__ float g_qwx[(size_t)Bv * Sv * 512];   // per token: [q(128) | wr(128) | xh0(256)]
__device__ float g_ba[(size_t)Bv * Sv * 64];     // precomputed attn2 softmax
__device__ float g_rx[(size_t)Bv * Sv * 384];    // per token: [read(128) | xh_final(256)]
__device__ __align__(256) __half g_h[591872];    // fp16 weight pack

#define H_QKV   0          // 2*256*768 = 393216
#define H_WO    393216     // 2*256*256 = 131072
#define H_BPW   524288     // 128*256   = 32768
#define H_SUPW  557056     // 256*128   = 32768
#define H_WBETA 589824     // 2*256*4   = 2048
#define H_TOTAL 591872

// smem float-index layout for k_rec
#define SM_SLOTS 0        // 8192
#define SM_PART  8192     // 3072
#define SM_QN    11264    // 128  (next-token q for fused logits)
#define SM_WR    11392    // 128
#define SM_XH    11520    // 256
#define SM_ABUF  11776    // 64
#define SM_A     11840    // 64
#define SM_BA    11904    // 64
#define SM_G2    11968    // 64
#define SM_CB    12032    // 64
#define SM_C1    12096    // 64
#define SM_C2    12160    // 64
#define SM_T1    12224    // 64
#define SM_BIND  12288    // 128
#define SM_QKV   12416    // 1536 = 2 sets x 768
#define SM_BETA  14208    // 4
#define SM_O     14212    // 256
#define SM_U     14468    // 256 = 2 x 128
#define SM_EXCH  14724    // 512 = 2 x 256
#define SM_WOUT  15236    // 512 = 2 x 256
#define SM_MV    15748    // 4
#define SM_BQKV2 15752    // 192
#define SM_BO2   15944    // 64
#define SM_LNG   16008    // 512
#define SM_LNB   16520    // 512
#define SM_BPB2  17032    // 32
#define SM_SUPB  17064    // 128
#define SM_BBETA 17192    // 8
#define SM_MBAR  17200    // 24 floats = 12 u64 mbarriers
#define SM_HBASE 17224    // halves start (16B aligned)
// half offsets (relative to half base)
#define WS_QKV  0         // 2*256*96 = 49152
#define WS_WO   49152     // 2*256*32 = 16384
#define WS_BP   65536     // 128*32   = 4096
#define WS_SUP  69632     // 256*16   = 4096
#define WS_BETA 73728     // 2*256*4  = 2048
#define SMEM_REC_BYTES (SM_HBASE * 4 + 75776 * 2)   // 220448

// ---- cluster / mbarrier helpers ----
__device__ __forceinline__ void cluster_sync_() {
    asm volatile("barrier.cluster.arrive.aligned;" ::: "memory");
    asm volatile("barrier.cluster.wait.aligned;" ::: "memory");
}
__device__ __forceinline__ void mbar_init(float* lmbar, unsigned cnt) {
    unsigned m = (unsigned)__cvta_generic_to_shared(lmbar);
    asm volatile("mbarrier.init.shared.b64 [%0], %1;" :: "r"(m), "r"(cnt) : "memory");
}
__device__ __forceinline__ void mbar_expect(float* lmbar, unsigned tx) {
    unsigned m = (unsigned)__cvta_generic_to_shared(lmbar);
    asm volatile("mbarrier.arrive.expect_tx.shared.b64 _, [%0], %1;" :: "r"(m), "r"(tx) : "memory");
}
// bounded-spin wait: never hangs the container
__device__ __forceinline__ void mbar_wait(float* lmbar, unsigned parity) {
    unsigned m = (unsigned)__cvta_generic_to_shared(lmbar);
    unsigned done = 0;
    long long t0 = clock64();
    while (!done) {
        asm volatile("{\n\t.reg .pred P;\n\t"
            "mbarrier.try_wait.parity.acquire.cluster.shared::cta.b64 P, [%1], %2, 0x989680;\n\t"
            "selp.b32 %0, 1, 0, P;\n\t}"
            : "=r"(done) : "r"(m), "r"(parity) : "memory");
        if (!done && (clock64() - t0) > 200000000LL) break;   // ~0.1 s watchdog
    }
}
__device__ __forceinline__ void st_async_f32(float* lptr, float* lmbar, int rr, float v) {
    unsigned a = (unsigned)__cvta_generic_to_shared(lptr);
    unsigned m = (unsigned)__cvta_generic_to_shared(lmbar);
    unsigned ra, rm;
    asm volatile("mapa.shared::cluster.u32 %0, %1, %2;" : "=r"(ra) : "r"(a), "r"(rr));
    asm volatile("mapa.shared::cluster.u32 %0, %1, %2;" : "=r"(rm) : "r"(m), "r"(rr));
    asm volatile("st.async.shared::cluster.mbarrier::complete_tx::bytes.b32 [%0], %1, [%2];"
                 :: "r"(ra), "r"(__float_as_uint(v)), "r"(rm) : "memory");
}
__device__ __forceinline__ void bcast_async(float* lptr, float* lmbar, float v) {
#pragma unroll
    for (int rr = 0; rr < CLW; rr++) st_async_f32(lptr, lmbar, rr, v);
}

// fp16 vec8 FMA helper
#define FMA8(w, xv) do { \
    half2 h0 = *(half2*)&(w).x, h1 = *(half2*)&(w).y, h2 = *(half2*)&(w).z, h3 = *(half2*)&(w).w; \
    a0 += (xv) * __low2float(h0); a1 += (xv) * __high2float(h0); \
    a2 += (xv) * __low2float(h1); a3 += (xv) * __high2float(h1); \
    a4 += (xv) * __low2float(h2); a5 += (xv) * __high2float(h2); \
    a6 += (xv) * __low2float(h3); a7 += (xv) * __high2float(h3); } while (0)

// ---------------------------------------------------------------------------
__global__ __launch_bounds__(512) void k_cvt(
    const float* __restrict__ wqkv, const float* __restrict__ wo,
    const float* __restrict__ bpw, const float* __restrict__ supw,
    const float* __restrict__ wbeta)
{
    int i = blockIdx.x * 512 + threadIdx.x;
    if (i >= H_TOTAL) return;
    float v;
    if (i < H_WO)        v = wqkv[i];
    else if (i < H_BPW)  v = wo[i - H_WO];
    else if (i < H_SUPW) v = bpw[i - H_BPW];
    else if (i < H_WBETA) v = supw[i - H_SUPW];
    else                 v = wbeta[i - H_WBETA];
    g_h[i] = __float2half(v);
}

// ---------------------------------------------------------------------------
__global__ __launch_bounds__(512) void k_pre(
    const float* __restrict__ x,
    const float* __restrict__ sb_wq, const float* __restrict__ sb_bq,
    const float* __restrict__ sb_ww, const float* __restrict__ sb_bw,
    const float* __restrict__ p_win, const float* __restrict__ p_bin)
{
    __shared__ float xs[16 * 512];
    const int t0 = blockIdx.x * 16;
    const int tid = threadIdx.x;
    const float* xb = x + (size_t)t0 * 512;
    for (int idx = tid; idx < 16 * 512; idx += 512) xs[idx] = xb[idx];
    __syncthreads();

    const int c = tid;
    const float* W; int ld; float bias;
    if (c < 128)      { W = sb_wq + c;         ld = 128; bias = sb_bq[c]; }
    else if (c < 256) { W = sb_ww + (c - 128); ld = 128; bias = sb_bw[c - 128]; }
    else              { W = p_win + (c - 256); ld = 256; bias = p_bin[c - 256]; }

    float acc[16];
#pragma unroll
    for (int t = 0; t < 16; t++) acc[t] = 0.f;
    for (int i = 0; i < 512; i++) {
        float w = W[(size_t)i * ld];
#pragma unroll
        for (int t = 0; t < 16; t++) acc[t] += xs[t * 512 + i] * w;
    }
#pragma unroll
    for (int t = 0; t < 16; t++)
        g_qwx[((size_t)(t0 + t)) * 512 + c] = acc[t] + bias;
}

// ---------------------------------------------------------------------------
__global__ __launch_bounds__(256) void k_ba(
    const float* __restrict__ b_wq, const float* __restrict__ b_bq,
    const float* __restrict__ b_keys)
{
    __shared__ float s_x[8 * 256];
    __shared__ float s_keys[64 * 129];
    __shared__ float s_bq[8 * 128];
    const int t0 = blockIdx.x * 8;
    const int tid = threadIdx.x;

    for (int idx = tid; idx < 8 * 256; idx += 256) {
        int t = idx >> 8, i = idx & 255;
        s_x[idx] = g_qwx[((size_t)(t0 + t)) * 512 + 256 + i];
    }
    for (int idx = tid; idx < 64 * 128; idx += 256) {
        int n = idx >> 7, k = idx & 127;
        s_keys[n * 129 + k] = b_keys[idx];
    }
    __syncthreads();

    {
        int c = tid & 127, tg = tid >> 7;
        float acc[4];
        float bb = b_bq[c];
#pragma unroll
        for (int t = 0; t < 4; t++) acc[t] = bb;
        for (int i = 0; i < 256; i++) {
            float w = b_wq[i * 128 + c];
#pragma unroll
            for (int t = 0; t < 4; t++) acc[t] += s_x[(tg * 4 + t) * 256 + i] * w;
        }
#pragma unroll
        for (int t = 0; t < 4; t++) s_bq[(tg * 4 + t) * 128 + c] = acc[t];
    }
    __syncthreads();

    {
        const float invscale = 0.08838834764831845f;
        int t = tid >> 5, lane = tid & 31;
        float l0 = 0.f, l1 = 0.f;
        for (int k = 0; k < 128; k++) {
            float q = s_bq[t * 128 + k];
            l0 += q * s_keys[lane * 129 + k];
            l1 += q * s_keys[(lane + 32) * 129 + k];
        }
        l0 *= invscale; l1 *= invscale;
        float m = fmaxf(l0, l1);
#pragma unroll
        for (int o = 16; o > 0; o >>= 1) m = fmaxf(m, __shfl_xor_sync(0xffffffffu, m, o));
        float e0 = expf(l0 - m), e1 = expf(l1 - m);
        float ssum = e0 + e1;
#pragma unroll
        for (int o = 16; o > 0; o >>= 1) ssum += __shfl_xor_sync(0xffffffffu, ssum, o);
        float inv = 1.f / ssum;
        float* dst = g_ba + ((size_t)(t0 + t)) * 64;
        dst[lane] = e0 * inv;
        dst[lane + 32] = e1 * inv;
    }
}

// ---------------------------------------------------------------------------
// Kernel 2: recurrent core. 64 CTAs = 8 batches x cluster of 8.
// SMEM-resident weight slices; st.async + mbarrier exchange (double-buffered);
// fused slot-update+next-logits; fused knorm+state.
// ---------------------------------------------------------------------------
__global__ __launch_bounds__(512, 1) __cluster_dims__(CLW, 1, 1)
void k_rec(
    const float* __restrict__ sb_init, const float* __restrict__ bp_b,
    const float* __restrict__ dn_bqkv, const float* __restrict__ dn_bbeta,
    const float* __restrict__ dn_bo, const float* __restrict__ dn_lng,
    const float* __restrict__ dn_lnb, const float* __restrict__ sup_b)
{
    extern __shared__ float sm[];
    __half* hs = (__half*)(sm + SM_HBASE);

    const int tid = threadIdx.x;
    const int b  = blockIdx.x / CLW;
    const int rk = blockIdx.x % CLW;
    const float invscale = 0.08838834764831845f;

    // ---- one-time init ----
    for (int idx = tid; idx < Nv * SDv; idx += 512) sm[SM_SLOTS + idx] = sb_init[idx];
    if (tid < 192) sm[SM_BQKV2 + tid] = dn_bqkv[(tid / 96) * 768 + rk * 96 + (tid % 96)];
    if (tid < 64)  sm[SM_BO2 + tid]   = dn_bo[(tid / 32) * 256 + rk * 32 + (tid % 32)];
    if (tid < 512) { sm[SM_LNG + tid] = dn_lng[tid]; sm[SM_LNB + tid] = dn_lnb[tid]; }
    if (tid < 32)  sm[SM_BPB2 + tid]  = bp_b[rk * 32 + tid];
    if (tid < 128) sm[SM_SUPB + tid]  = sup_b[tid];
    if (tid < 8)   sm[SM_BBETA + tid] = dn_bbeta[tid];
    if (tid == 0) {
        for (int i = 0; i < 12; i++) mbar_init(sm + SM_MBAR + i * 2, 1u);
    }

    {   // qkv slice: 6144 uint4
        const uint4* src = (const uint4*)(g_h + H_QKV);
        uint4* dst = (uint4*)(hs + WS_QKV);
        for (int i = tid; i < 6144; i += 512) {
            int rowL = i / 12, c = i % 12;
            dst[rowL * 12 + c] = src[(size_t)rowL * 96 + rk * 12 + c];
        }
    }
    {   // wo slice: 2048 uint4
        const uint4* src = (const uint4*)(g_h + H_WO);
        uint4* dst = (uint4*)(hs + WS_WO);
        for (int i = tid; i < 2048; i += 512) {
            int rowL = i / 4, c = i % 4;
            dst[rowL * 4 + c] = src[(size_t)rowL * 32 + rk * 4 + c];
        }
    }
    {   // bp slice: 512 uint4
        const uint4* src = (const uint4*)(g_h + H_BPW);
        uint4* dst = (uint4*)(hs + WS_BP);
        for (int i = tid; i < 512; i += 512) {
            int row = i / 4, c = i % 4;
            dst[row * 4 + c] = src[(size_t)row * 32 + rk * 4 + c];
        }
    }
    {   // sup slice: 512 uint4
        const uint4* src = (const uint4*)(g_h + H_SUPW);
        uint4* dst = (uint4*)(hs + WS_SUP);
        for (int i = tid; i < 512; i += 512) {
            int row = i / 2, c = i % 2;
            dst[row * 2 + c] = src[(size_t)row * 16 + rk * 2 + c];
        }
    }
    {   // wbeta replicated: 256 uint4
        const uint4* src = (const uint4*)(g_h + H_WBETA);
        uint4* dst = (uint4*)(hs + WS_BETA);
        for (int i = tid; i < 256; i += 512) dst[i] = src[i];
    }

    float Sreg[64];
#pragma unroll
    for (int j = 0; j < 64; j++) Sreg[j] = 0.f;
    const int l_own = tid >> 8;
    const int h_own = (tid >> 6) & 3;
    const int i_own = tid & 63;
    const int wp = tid >> 5, la = tid & 31;
    __syncthreads();
    cluster_sync_();   // mbarrier init visible cluster-wide

    // token prefetch registers (step 0)
    float pf_q = g_qwx[(size_t)(b * Sv) * 512 + tid];
    float pf_b = (tid < 64) ? g_ba[(size_t)(b * Sv) * 64 + tid] : 0.f;
    if (tid < 128) sm[SM_QN + tid] = pf_q;   // q0 for standalone logits at s=0

    for (int s = 0; s < Sv; ++s) {
        const size_t tok = (size_t)(b * Sv + s);
        const int set = s & 1;
        const unsigned par = (unsigned)((s >> 1) & 1);
        float* MB = sm + SM_MBAR + set * 2;

        // --- arm this step's barriers (tid 0) ---
        if (tid == 0) {
            mbar_expect(MB + 0 * 4, 1024u);   // bp
            mbar_expect(MB + 1 * 4, 3072u);   // qkv l0
            mbar_expect(MB + 2 * 4, 1024u);   // wo  l0
            mbar_expect(MB + 3 * 4, 3072u);   // qkv l1
            mbar_expect(MB + 4 * 4, 1024u);   // wo  l1
            mbar_expect(MB + 5 * 4, 512u);    // u
        }

        // --- A: commit prefetched token data (q no longer staged) ---
        if (tid >= 128 && tid < 256) sm[SM_WR + tid - 128] = pf_q;
        else if (tid >= 256) sm[SM_XH + tid - 256] = pf_q;
        if (tid < 64) {
            sm[SM_BA + tid] = pf_b;
            sm[SM_G2 + tid] = 1.f / (1.f + expf(-pf_b));
        }
        __syncthreads();
        // prefetch next token
        if (s + 1 < Sv) {
            pf_q = g_qwx[(tok + 1) * 512 + tid];
            if (tid < 64) pf_b = g_ba[(tok + 1) * 64 + tid];
        }

        // --- preload D's slot operands (hidden under C / standalone-B) ---
        float sv[16];
        {
            int d = tid & 127, ch = tid >> 7;
#pragma unroll
            for (int k = 0; k < 16; k++) sv[k] = sm[SM_SLOTS + (ch * 16 + k) * 128 + d];
        }

        // --- B (only s==0): standalone attn1 logits from SM_QN ---
        if (s == 0) {
#pragma unroll
            for (int r = 0; r < 4; r++) {
                int n = wp * 4 + r;
                const float* row = sm + SM_SLOTS + n * 128;
                float p = row[la] * sm[SM_QN + la] + row[la + 32] * sm[SM_QN + la + 32]
                        + row[la + 64] * sm[SM_QN + la + 64] + row[la + 96] * sm[SM_QN + la + 96];
#pragma unroll
                for (int o = 16; o > 0; o >>= 1) p += __shfl_xor_sync(0xffffffffu, p, o);
                if (la == 0) sm[SM_ABUF + n] = p * invscale;
            }
            __syncthreads();
        }

        // --- C: softmax + per-n coefficients (warp 0); ABUF from prev U ---
        if (tid < 32) {
            float l0 = sm[SM_ABUF + tid], l1 = sm[SM_ABUF + tid + 32];
            float m = fmaxf(l0, l1);
#pragma unroll
            for (int o = 16; o > 0; o >>= 1) m = fmaxf(m, __shfl_xor_sync(0xffffffffu, m, o));
            float e0 = expf(l0 - m), e1 = expf(l1 - m);
            float ss = e0 + e1;
#pragma unroll
            for (int o = 16; o > 0; o >>= 1) ss += __shfl_xor_sync(0xffffffffu, ss, o);
            float inv = 1.f / ss;
            float a0 = e0 * inv, a1 = e1 * inv;
            float g0 = 1.f / (1.f + expf(-a0)), g1 = 1.f / (1.f + expf(-a1));
            float ba0 = sm[SM_BA + tid], ba1 = sm[SM_BA + tid + 32];
            float g20 = sm[SM_G2 + tid], g21 = sm[SM_G2 + tid + 32];
            sm[SM_A + tid] = a0;  sm[SM_A + tid + 32] = a1;
            sm[SM_CB + tid] = ba0 * (1.f - g0);         sm[SM_CB + tid + 32] = ba1 * (1.f - g1);
            sm[SM_C1 + tid] = (1.f - g20) * (1.f - g0); sm[SM_C1 + tid + 32] = (1.f - g21) * (1.f - g1);
            sm[SM_C2 + tid] = (1.f - g20) * g0 * a0;    sm[SM_C2 + tid + 32] = (1.f - g21) * g1 * a1;
            sm[SM_T1 + tid] = g20 * ba0;                sm[SM_T1 + tid + 32] = g21 * ba1;
            float cw = ba0 * g0 * a0 + ba1 * g1 * a1;
#pragma unroll
            for (int o = 16; o > 0; o >>= 1) cw += __shfl_xor_sync(0xffffffffu, cw, o);
            if (tid == 0) sm[SM_MV + 2] = cw;
        }
        __syncthreads();

        // --- D: read (rk0 only) + bind partials from preloaded sv ---
        {
            int d = tid & 127, ch = tid >> 7;
            float pb0 = 0.f, pb1 = 0.f;
#pragma unroll
            for (int k = 0; k < 16; k += 2) {
                int n0 = ch * 16 + k;
                pb0 += sm[SM_CB + n0] * sv[k];
                pb1 += sm[SM_CB + n0 + 1] * sv[k + 1];
            }
            sm[SM_PART + 512 + ch * 128 + d] = pb0 + pb1;
            if (rk == 0) {
                float pr0 = 0.f, pr1 = 0.f;
#pragma unroll
                for (int k = 0; k < 16; k += 2) {
                    int n0 = ch * 16 + k;
                    pr0 += sm[SM_A + n0] * sv[k];
                    pr1 += sm[SM_A + n0 + 1] * sv[k + 1];
                }
                sm[SM_PART + ch * 128 + d] = pr0 + pr1;
            }
        }
        __syncthreads();
        // --- E: reduce read (export, rk0) + bind ---
        if (tid < 128) {
            if (rk == 0) {
                float rv = sm[SM_PART + tid] + sm[SM_PART + 128 + tid]
                         + sm[SM_PART + 256 + tid] + sm[SM_PART + 384 + tid];
                g_rx[tok * 384 + tid] = rv;
            }
            float bv = (sm[SM_PART + 512 + tid] + sm[SM_PART + 640 + tid])
                     + (sm[SM_PART + 768 + tid] + sm[SM_PART + 896 + tid])
                     + sm[SM_MV + 2] * sm[SM_WR + tid];
            sm[SM_BIND + tid] = bv;
        }
        __syncthreads();

        // --- F: bp GEMV ---
        if (tid < 128) {
            int cg = tid & 3, iseg = tid >> 2;
            const uint4* W = (const uint4*)(hs + WS_BP) + cg;
            float a0=0,a1=0,a2=0,a3=0,a4=0,a5=0,a6=0,a7=0;
#pragma unroll
            for (int r = 0; r < 4; r++) {
                int row = iseg + 32 * r;
                float xv = sm[SM_BIND + row];
                uint4 w = W[row * 4];
                FMA8(w, xv);
            }
            float* P = sm + SM_PART + iseg * 32 + cg * 8;
            P[0]=a0; P[1]=a1; P[2]=a2; P[3]=a3; P[4]=a4; P[5]=a5; P[6]=a6; P[7]=a7;
        }
        __syncthreads();
        // --- G: reduce + async exchange ---
        if (tid < 32) {
            float p0 = sm[SM_BPB2 + tid], p1 = 0.f, p2 = 0.f, p3 = 0.f;
#pragma unroll
            for (int sg = 0; sg < 32; sg += 4) {
                p0 += sm[SM_PART + sg * 32 + tid];
                p1 += sm[SM_PART + (sg + 1) * 32 + tid];
                p2 += sm[SM_PART + (sg + 2) * 32 + tid];
                p3 += sm[SM_PART + (sg + 3) * 32 + tid];
            }
            bcast_async(sm + SM_EXCH + set * 256 + rk * 32 + tid, MB + 0 * 4, (p0 + p1) + (p2 + p3));
        }
        mbar_wait(MB + 0 * 4, par);
        // --- H: xh += exch ---
        if (tid < 256) sm[SM_XH + tid] += sm[SM_EXCH + set * 256 + tid];
        __syncthreads();

        // --- DeltaNet layers ---
#pragma unroll
        for (int l = 0; l < 2; l++) {
            // I: qkv GEMV + beta
            if (tid < 384) {
                int cg = tid % 12, iseg = tid / 12;
                const uint4* W = (const uint4*)(hs + WS_QKV) + (size_t)l * 3072 + cg;
                float a0=0,a1=0,a2=0,a3=0,a4=0,a5=0,a6=0,a7=0;
#pragma unroll
                for (int r = 0; r < 8; r++) {
                    int row = iseg + 32 * r;
                    float xv = sm[SM_XH + row];
                    uint4 w = W[row * 12];
                    FMA8(w, xv);
                }
                float* P = sm + SM_PART + iseg * 96 + cg * 8;
                P[0]=a0; P[1]=a1; P[2]=a2; P[3]=a3; P[4]=a4; P[5]=a5; P[6]=a6; P[7]=a7;
            } else {
                int c = (tid - 384) >> 5;
                const __half* Wb = hs + WS_BETA + l * 1024;
                float acc = 0.f;
#pragma unroll
                for (int j = 0; j < 8; j++) {
                    int row = la + 32 * j;
                    acc += sm[SM_XH + row] * __half2float(Wb[row * 4 + c]);
                }
#pragma unroll
                for (int o = 16; o > 0; o >>= 1) acc += __shfl_xor_sync(0xffffffffu, acc, o);
                if (la == 0) {
                    float z = acc + sm[SM_BBETA + l * 4 + c];
                    sm[SM_BETA + c] = 1.f / (1.f + expf(-z));
                }
            }
            __syncthreads();
            // J: reduce + async exchange qkv
            if (tid < 96) {
                float p0 = sm[SM_BQKV2 + l * 96 + tid], p1 = 0.f, p2 = 0.f, p3 = 0.f;
#pragma unroll
                for (int sg = 0; sg < 32; sg += 4) {
                    p0 += sm[SM_PART + sg * 96 + tid];
                    p1 += sm[SM_PART + (sg + 1) * 96 + tid];
                    p2 += sm[SM_PART + (sg + 2) * 96 + tid];
                    p3 += sm[SM_PART + (sg + 3) * 96 + tid];
                }
                bcast_async(sm + SM_QKV + set * 768 + rk * 96 + tid, MB + (1 + 2 * l) * 4, (p0 + p1) + (p2 + p3));
            }
            mbar_wait(MB + (1 + 2 * l) * 4, par);
            const float* qkvb = sm + SM_QKV + set * 768;

            // M: fused k-norm + state update (owners of layer l)
            if (l_own == l) {
                const float* kr = qkvb + 256 + h_own * 64;
                const float* qh = qkvb + h_own * 64;
                float n0 = 0.f, n1 = 0.f, n2 = 0.f, n3 = 0.f;
                float s0 = 0.f, s1 = 0.f, s2 = 0.f, s3 = 0.f;
#pragma unroll
                for (int j = 0; j < 64; j += 4) {
                    float k0 = kr[j], k1 = kr[j + 1], k2 = kr[j + 2], k3 = kr[j + 3];
                    n0 += k0 * k0; n1 += k1 * k1; n2 += k2 * k2; n3 += k3 * k3;
                    s0 += Sreg[j] * k0;     s1 += Sreg[j + 1] * k1;
                    s2 += Sreg[j + 2] * k2; s3 += Sreg[j + 3] * k3;
                }
                float inv = 1.f / (sqrtf((n0 + n1) + (n2 + n3)) + 1e-6f);
                float sk = ((s0 + s1) + (s2 + s3)) * inv;
                float delta = sm[SM_BETA + h_own] * (qkvb[512 + h_own * 64 + i_own] - sk);
                float d2 = delta * inv;
                float o0 = 0.f, o1 = 0.f, o2 = 0.f, o3 = 0.f;
#pragma unroll
                for (int j = 0; j < 64; j += 4) {
                    Sreg[j]     += d2 * kr[j];     o0 += Sreg[j] * qh[j];
                    Sreg[j + 1] += d2 * kr[j + 1]; o1 += Sreg[j + 1] * qh[j + 1];
                    Sreg[j + 2] += d2 * kr[j + 2]; o2 += Sreg[j + 2] * qh[j + 2];
                    Sreg[j + 3] += d2 * kr[j + 3]; o3 += Sreg[j + 3] * qh[j + 3];
                }
                sm[SM_O + h_own * 64 + i_own] = (o0 + o1) + (o2 + o3);
            }
            __syncthreads();
            // N: wo GEMV
            if (tid < 256) {
                int cg = tid & 3, iseg = tid >> 2;
                const uint4* W = (const uint4*)(hs + WS_WO) + (size_t)l * 1024 + cg;
                float a0=0,a1=0,a2=0,a3=0,a4=0,a5=0,a6=0,a7=0;
#pragma unroll
                for (int r = 0; r < 4; r++) {
                    int row = iseg + 64 * r;
                    float xv = sm[SM_O + row];
                    uint4 w = W[row * 4];
                    FMA8(w, xv);
                }
                float* P = sm + SM_PART + iseg * 32 + cg * 8;
                P[0]=a0; P[1]=a1; P[2]=a2; P[3]=a3; P[4]=a4; P[5]=a5; P[6]=a6; P[7]=a7;
            }
            __syncthreads();
            // O: reduce + async exchange
            if (tid < 32) {
                float p0 = sm[SM_BO2 + l * 32 + tid], p1 = 0.f, p2 = 0.f, p3 = 0.f;
#pragma unroll
                for (int sg = 0; sg < 64; sg += 4) {
                    p0 += sm[SM_PART + sg * 32 + tid];
                    p1 += sm[SM_PART + (sg + 1) * 32 + tid];
                    p2 += sm[SM_PART + (sg + 2) * 32 + tid];
                    p3 += sm[SM_PART + (sg + 3) * 32 + tid];
                }
                bcast_async(sm + SM_WOUT + set * 256 + rk * 32 + tid, MB + (2 + 2 * l) * 4, (p0 + p1) + (p2 + p3));
            }
            mbar_wait(MB + (2 + 2 * l) * 4, par);
            const float* woutb = sm + SM_WOUT + set * 256;

            // Q: LN stats from xh+wout (warp 0)
            if (tid < 32) {
                float s1 = 0.f, s2 = 0.f;
#pragma unroll
                for (int k = 0; k < 8; k++) {
                    float v = sm[SM_XH + tid * 8 + k] + woutb[tid * 8 + k];
                    s1 += v; s2 += v * v;
                }
#pragma unroll
                for (int o = 16; o > 0; o >>= 1) {
                    s1 += __shfl_xor_sync(0xffffffffu, s1, o);
                    s2 += __shfl_xor_sync(0xffffffffu, s2, o);
                }
                if (tid == 0) {
                    float m = s1 / 256.f;
                    float var = s2 / 256.f - m * m;
                    sm[SM_MV + 0] = m; sm[SM_MV + 1] = rsqrtf(var + 1e-5f);
                }
            }
            __syncthreads();
            // R: normalize (resid inline)
            if (tid < 256) {
                float r = sm[SM_XH + tid] + woutb[tid];
                sm[SM_XH + tid] = (r - sm[SM_MV + 0]) * sm[SM_MV + 1]
                                * sm[SM_LNG + l * 256 + tid] + sm[SM_LNB + l * 256 + tid];
            }
            __syncthreads();
        }

        // --- S: sup GEMV + stage q_{s+1} + xh export (rk0) ---
        if (tid < 128) {
            sm[SM_QN + tid] = pf_q;   // next-token q for fused logits in U
            int cg = tid & 1, iseg = tid >> 1;
            const uint4* W = (const uint4*)(hs + WS_SUP) + cg;
            float a0=0,a1=0,a2=0,a3=0,a4=0,a5=0,a6=0,a7=0;
#pragma unroll
            for (int r = 0; r < 4; r++) {
                int row = iseg + 64 * r;
                float xv = sm[SM_XH + row];
                uint4 w = W[row * 2];
                FMA8(w, xv);
            }
            float* P = sm + SM_PART + iseg * 16 + cg * 8;
            P[0]=a0; P[1]=a1; P[2]=a2; P[3]=a3; P[4]=a4; P[5]=a5; P[6]=a6; P[7]=a7;
        } else if (tid >= 256 && rk == 0) {
            g_rx[tok * 384 + 128 + (tid - 256)] = sm[SM_XH + tid - 256];
        }
        __syncthreads();
        // --- T: reduce + async exchange u ---
        if (tid < 16) {
            float p0 = 0.f, p1 = 0.f, p2 = 0.f, p3 = 0.f;
#pragma unroll
            for (int sg = 0; sg < 64; sg += 4) {
                p0 += sm[SM_PART + sg * 16 + tid];
                p1 += sm[SM_PART + (sg + 1) * 16 + tid];
                p2 += sm[SM_PART + (sg + 2) * 16 + tid];
                p3 += sm[SM_PART + (sg + 3) * 16 + tid];
            }
            bcast_async(sm + SM_U + set * 128 + rk * 16 + tid, MB + 5 * 4, (p0 + p1) + (p2 + p3));
        }
        mbar_wait(MB + 5 * 4, par);
        // --- U: fused slot update + next-step attn1 logits ---
        {
            const float* ub = sm + SM_U + set * 128;
            float w0 = sm[SM_WR + la],       w1 = sm[SM_WR + la + 32],
                  w2 = sm[SM_WR + la + 64],  w3 = sm[SM_WR + la + 96];
            float u0 = ub[la],      u1 = ub[la + 32],
                  u2 = ub[la + 64], u3 = ub[la + 96];
            float b0 = sm[SM_SUPB + la],      b1 = sm[SM_SUPB + la + 32],
                  b2 = sm[SM_SUPB + la + 64], b3 = sm[SM_SUPB + la + 96];
            float q0 = sm[SM_QN + la],      q1 = sm[SM_QN + la + 32],
                  q2 = sm[SM_QN + la + 64], q3 = sm[SM_QN + la + 96];
#pragma unroll
            for (int r = 0; r < 4; r++) {
                int n = wp * 4 + r;
                float c1 = sm[SM_C1 + n], c2 = sm[SM_C2 + n];
                float t1 = sm[SM_T1 + n], g2 = sm[SM_G2 + n];
                float* row = sm + SM_SLOTS + n * 128;
                float s0 = c1 * row[la]      + c2 * w0 + t1 * u0 + g2 * b0;
                float s1 = c1 * row[la + 32] + c2 * w1 + t1 * u1 + g2 * b1;
                float s2 = c1 * row[la + 64] + c2 * w2 + t1 * u2 + g2 * b2;
                float s3 = c1 * row[la + 96] + c2 * w3 + t1 * u3 + g2 * b3;
                row[la] = s0; row[la + 32] = s1; row[la + 64] = s2; row[la + 96] = s3;
                float p = s0 * q0 + s1 * q1 + s2 * q2 + s3 * q3;
#pragma unroll
                for (int o = 16; o > 0; o >>= 1) p += __shfl_xor_sync(0xffffffffu, p, o);
                if (la == 0) sm[SM_ABUF + n] = p * invscale;
            }
        }
        __syncthreads();
    }
    cluster_sync_();   // keep cluster resident until all remote stores landed
}

// ---------------------------------------------------------------------------
__global__ __launch_bounds__(512) void k_out(
    const float* __restrict__ sb_wo, const float* __restrict__ sb_bo,
    const float* __restrict__ op_w, const float* __restrict__ op_b,
    const float* __restrict__ oln_g, const float* __restrict__ oln_b,
    const float* __restrict__ ow, const float* __restrict__ ob,
    float* __restrict__ out)
{
    __shared__ float rx[8 * 384];
    __shared__ float yt[8 * 512];
    __shared__ float mv[8][2];
    const int t0 = blockIdx.x * 8;
    const int tid = threadIdx.x;
    const float* src = g_rx + (size_t)t0 * 384;
    for (int idx = tid; idx < 8 * 384; idx += 512) rx[idx] = src[idx];
    __syncthreads();

    {
        float acc[8];
        float bias = sb_bo[tid] + op_b[tid];
#pragma unroll
        for (int t = 0; t < 8; t++) acc[t] = bias;
        const float* w1 = sb_wo + tid;
        for (int i = 0; i < 128; i++) {
            float wv = w1[(size_t)i * 512];
#pragma unroll
            for (int t = 0; t < 8; t++) acc[t] += rx[t * 384 + i] * wv;
        }
        const float* w2 = op_w + tid;
        for (int i = 0; i < 256; i++) {
            float wv = w2[(size_t)i * 512];
#pragma unroll
            for (int t = 0; t < 8; t++) acc[t] += rx[t * 384 + 128 + i] * wv;
        }
#pragma unroll
        for (int t = 0; t < 8; t++) yt[t * 512 + tid] = acc[t];
    }
    __syncthreads();

    if (tid < 256) {
        int tt = tid >> 5, lane = tid & 31;
        float s1 = 0.f, s2 = 0.f;
        for (int i = lane; i < 512; i += 32) { float v = yt[tt * 512 + i]; s1 += v; s2 += v * v; }
#pragma unroll
        for (int o = 16; o > 0; o >>= 1) {
            s1 += __shfl_xor_sync(0xffffffffu, s1, o);
            s2 += __shfl_xor_sync(0xffffffffu, s2, o);
        }
        if (lane == 0) {
            float m = s1 / 512.f;
            mv[tt][0] = m;
            mv[tt][1] = rsqrtf(s2 / 512.f - m * m + 1e-5f);
        }
    }
    __syncthreads();
    for (int idx = tid; idx < 8 * 512; idx += 512) {
        int tt = idx >> 9, c = idx & 511;
        yt[idx] = (yt[idx] - mv[tt][0]) * mv[tt][1] * oln_g[c] + oln_b[c];
    }
    __syncthreads();

    float acc[8];
#pragma unroll
    for (int t = 0; t < 8; t++) acc[t] = ob[tid];
    const float* w = ow + tid;
    for (int i = 0; i < 512; i++) {
        float wv = w[(size_t)i * 512];
#pragma unroll
        for (int t = 0; t < 8; t++) acc[t] += yt[t * 512 + i] * wv;
    }
    float* dst = out + (size_t)t0 * 512;
#pragma unroll
    for (int t = 0; t < 8; t++) dst[t * 512 + tid] = acc[t];
}

// ---------------------------------------------------------------------------
extern "C" void kernel_launch(void* const* d_in, const int* in_sizes, int n_in,
                              void* d_out, int out_size)
{
    const float* x        = (const float*)d_in[0];
    const float* sb_init  = (const float*)d_in[1];
    const float* sb_wq    = (const float*)d_in[2];
    const float* sb_bq    = (const float*)d_in[3];
    const float* sb_ww    = (const float*)d_in[4];
    const float* sb_bw    = (const float*)d_in[5];
    const float* sb_wo    = (const float*)d_in[6];
    const float* sb_bo    = (const float*)d_in[7];
    const float* p_win    = (const float*)d_in[8];
    const float* p_bin    = (const float*)d_in[9];
    const float* b_wq     = (const float*)d_in[10];
    const float* b_bq     = (const float*)d_in[11];
    const float* b_keys   = (const float*)d_in[12];
    const float* bp_w     = (const float*)d_in[13];
    const float* bp_b     = (const float*)d_in[14];
    const float* dn_wqkv  = (const float*)d_in[15];
    const float* dn_bqkv  = (const float*)d_in[16];
    const float* dn_wbeta = (const float*)d_in[17];
    const float* dn_bbeta = (const float*)d_in[18];
    const float* dn_wo    = (const float*)d_in[19];
    const float* dn_bo    = (const float*)d_in[20];
    const float* dn_lng   = (const float*)d_in[21];
    const float* dn_lnb   = (const float*)d_in[22];
    const float* sup_w    = (const float*)d_in[23];
    const float* sup_b    = (const float*)d_in[24];
    const float* op_w     = (const float*)d_in[25];
    const float* op_b     = (const float*)d_in[26];
    const float* oln_g    = (const float*)d_in[27];
    const float* oln_b    = (const float*)d_in[28];
    const float* ow       = (const float*)d_in[29];
    const float* ob       = (const float*)d_in[30];

    static bool attr_set = false;
    if (!attr_set) {
        cudaFuncSetAttribute(k_rec, cudaFuncAttributeMaxDynamicSharedMemorySize, SMEM_REC_BYTES);
        attr_set = true;
    }

    k_cvt<<<(H_TOTAL + 511) / 512, 512>>>(dn_wqkv, dn_wo, bp_w, sup_w, dn_wbeta);
    k_pre<<<512, 512>>>(x, sb_wq, sb_bq, sb_ww, sb_bw, p_win, p_bin);
    k_ba<<<1024, 256>>>(b_wq, b_bq, b_keys);
    k_rec<<<Bv * CLW, 512, SMEM_REC_BYTES>>>(sb_init, bp_b, dn_bqkv, dn_bbeta, dn_bo,
                                             dn_lng, dn_lnb, sup_b);
    k_out<<<1024, 512>>>(sb_wo, sb_bo, op_w, op_b, oln_g, oln_b, ow, ob, (float*)d_out);
}